// round 7
// baseline (speedup 1.0000x reference)
#include <cuda_runtime.h>
#include <cuda_bf16.h>
#include <stdint.h>

// Problem constants
#define B_TOT   4096
#define T_      64
#define D_      250
#define K_      1000
#define H_      125
#define NT      4
#define NL      50

// Tiling
#define BM      32
#define BN      128
#define KCH     64
#define NCHUNK  16
#define THREADS 512
#define HSS     132

// smem layout (bytes)
#define OFF_A    0                    // [buf2][hi|lo 4096 each] -> 16384
#define OFF_B    16384                // [buf2][hi/lo] 16384 each -> 65536
#define SMEM_TOTAL (OFF_B + 4*16384)  // 81920
#define OFF_HS   OFF_B                // epilogue: Hs[32][HSS] f32
#define OFF_W2S  (OFF_B + 16896)      // W2 cache

#define SW128(x) ((x) ^ ((((uint32_t)(x)) >> 3) & 0x70))

// Pre-split, pre-swizzled W1 images: [half][hi/lo][chunk][16384B]
__device__ __align__(16) uint8_t g_wbf[(size_t)2 * 2 * 16 * 16384];
// Pre-gathered, pre-split A images: [mblk128][chunk16][hi 4096 | lo 4096]
__device__ __align__(16) uint8_t g_abf[(size_t)128 * 16 * 8192];

__device__ __forceinline__ uint32_t smem_u32(const void* p) {
    uint32_t a;
    asm("{ .reg .u64 t; cvta.to.shared.u64 t, %1; cvt.u32.u64 %0, t; }"
        : "=r"(a) : "l"(p));
    return a;
}
__device__ __forceinline__ void ldsm4(uint32_t r[4], uint32_t a) {
    asm volatile("ldmatrix.sync.aligned.m8n8.x4.shared.b16 {%0,%1,%2,%3}, [%4];"
        : "=r"(r[0]), "=r"(r[1]), "=r"(r[2]), "=r"(r[3]) : "r"(a));
}
__device__ __forceinline__ void ldsm4t(uint32_t r[4], uint32_t a) {
    asm volatile("ldmatrix.sync.aligned.m8n8.x4.trans.shared.b16 {%0,%1,%2,%3}, [%4];"
        : "=r"(r[0]), "=r"(r[1]), "=r"(r[2]), "=r"(r[3]) : "r"(a));
}
__device__ __forceinline__ void mma16816(float c[4], const uint32_t a[4],
                                         uint32_t b0, uint32_t b1) {
    asm volatile(
        "mma.sync.aligned.m16n8k16.row.col.f32.bf16.bf16.f32 "
        "{%0,%1,%2,%3}, {%4,%5,%6,%7}, {%8,%9}, {%0,%1,%2,%3};"
        : "+f"(c[0]), "+f"(c[1]), "+f"(c[2]), "+f"(c[3])
        : "r"(a[0]), "r"(a[1]), "r"(a[2]), "r"(a[3]), "r"(b0), "r"(b1));
}
__device__ __forceinline__ void cp_async16(uint32_t s, const void* g) {
    asm volatile("cp.async.cg.shared.global [%0], [%1], 16;" :: "r"(s), "l"(g) : "memory");
}
__device__ __forceinline__ void cp_commit() {
    asm volatile("cp.async.commit_group;" ::: "memory");
}
template <int N> __device__ __forceinline__ void cp_wait() {
    asm volatile("cp.async.wait_group %0;" :: "n"(N) : "memory");
}

// ------- merged prep: blocks [0,512) split W1, blocks [512,1536) gather+split A ----
__global__ void prep_kernel(const float* __restrict__ W1t,
                            const float* __restrict__ W1r,
                            const float* __restrict__ lstm_out,
                            const int*   __restrict__ stack_index,
                            const int*   __restrict__ stack_len,
                            const int*   __restrict__ buffer_index,
                            const int*   __restrict__ buffer_len)
{
    if (blockIdx.x < 512) {
        // ---- W part ----
        int idx  = blockIdx.x * 256 + threadIdx.x;   // 0..131071
        int np   = idx & 63;
        int k    = (idx >> 6) & 1023;
        int half = idx >> 16;
        const float* W1 = half ? W1r : W1t;

        int n0 = np * 2;
        float w0 = 0.f, w1 = 0.f;
        if (k < K_) {
            if (n0 < H_)     w0 = W1[k * H_ + n0];
            if (n0 + 1 < H_) w1 = W1[k * H_ + n0 + 1];
        }
        __nv_bfloat16 h0 = __float2bfloat16(w0);
        __nv_bfloat16 h1 = __float2bfloat16(w1);
        __nv_bfloat16 l0 = __float2bfloat16(w0 - __bfloat162float(h0));
        __nv_bfloat16 l1 = __float2bfloat16(w1 - __bfloat162float(h1));

        int chunk = k >> 6, kloc = k & 63;
        int panel = n0 >> 6, nloc = n0 & 63;
        uint32_t sw = SW128((uint32_t)(kloc * 128 + nloc * 2));
        size_t ohi = ((size_t)(half * 2 + 0) * 16 + chunk) * 16384 + panel * 8192 + sw;
        size_t olo = ((size_t)(half * 2 + 1) * 16 + chunk) * 16384 + panel * 8192 + sw;

        *(__nv_bfloat162*)(g_wbf + ohi) = __halves2bfloat162(h0, h1);
        *(__nv_bfloat162*)(g_wbf + olo) = __halves2bfloat162(l0, l1);
    } else {
        // ---- A part ----
        int gid = (blockIdx.x - 512) * 256 + threadIdx.x;   // 0..262143
        int m   = gid >> 6;                                 // 0..4095
        int kq  = (gid & 63) * 16;                          // base k (8 pairs)

        int sl = stack_len[m];
        int bl = buffer_len[m];

        #pragma unroll
        for (int p = 0; p < 8; ++p) {
            int k = kq + p * 2;
            float2 v = make_float2(0.f, 0.f);
            if (k < K_) {
                int slot = k / D_;
                int d    = k - slot * D_;
                int off  = -1;
                if (slot < 3) { if (slot < sl) off = (m * T_ + stack_index[m * 3 + slot]) * D_; }
                else          { if (0 < bl)    off = (m * T_ + buffer_index[m]) * D_; }
                if (off >= 0) v = *(const float2*)(lstm_out + off + d);
            }
            __nv_bfloat16 hx = __float2bfloat16(v.x);
            __nv_bfloat16 hy = __float2bfloat16(v.y);
            __nv_bfloat16 lx = __float2bfloat16(v.x - __bfloat162float(hx));
            __nv_bfloat16 ly = __float2bfloat16(v.y - __bfloat162float(hy));

            int chunk = k >> 6, kloc = k & 63;
            size_t base = ((size_t)((m >> 5) * 16 + chunk)) * 8192;
            uint32_t sw = SW128((uint32_t)((m & 31) * 128 + (kloc >> 1) * 4));
            *(__nv_bfloat162*)(g_abf + base + sw)        = __halves2bfloat162(hx, hy);
            *(__nv_bfloat162*)(g_abf + base + 4096 + sw) = __halves2bfloat162(lx, ly);
        }
    }
}

// ---------------- main kernel: 512 threads, 16 warps, warp tile 16x16 ----------
__global__ __launch_bounds__(THREADS, 2)
void parser_hmma_kernel(const float* __restrict__ b1t,
                        const float* __restrict__ W2t,
                        const float* __restrict__ b2t,
                        const float* __restrict__ b1r,
                        const float* __restrict__ W2r,
                        const float* __restrict__ b2r,
                        float* __restrict__ out)
{
    extern __shared__ char smem[];
    const uint32_t sb = smem_u32(smem);
    const int tid  = threadIdx.x;
    const int wid  = tid >> 5;
    const int lane = tid & 31;
    const int wm   = wid & 1;          // M group: rows wm*16 .. +15
    const int wn   = wid >> 1;         // N group (0..7): cols wn*16 .. +15
    const int b0   = blockIdx.x * BM;
    const int half = blockIdx.y;

    // per-lane ldmatrix geometry
    const int g = lane >> 3, r8 = lane & 7;
    const int arow  = wm * 16 + (g & 1) * 8 + r8;        // A: 16 rows
    const int acolk = (g >> 1) * 8;                      // + kb
    const int brow  = (g & 1) * 8 + r8;                  // B: + kb
    const int bcol  = ((wn * 16) & 63) + (g >> 1) * 8;   // within panel
    const uint32_t bpanel = (uint32_t)(wn >> 2) * 8192;

    float acc[2][4];
    #pragma unroll
    for (int j = 0; j < 2; ++j)
        #pragma unroll
        for (int e = 0; e < 4; ++e) acc[j][e] = 0.f;

    auto fillB = [&](int c) {
        int buf = c & 1;
        uint32_t dh = sb + OFF_B + (buf * 2 + 0) * 16384;
        uint32_t dl = sb + OFF_B + (buf * 2 + 1) * 16384;
        const uint8_t* sh = g_wbf + ((size_t)(half * 2 + 0) * 16 + c) * 16384;
        const uint8_t* sl = g_wbf + ((size_t)(half * 2 + 1) * 16 + c) * 16384;
        #pragma unroll
        for (int it = 0; it < 2; ++it) {
            int o = (it * THREADS + tid) * 16;
            cp_async16(dh + o, sh + o);
            cp_async16(dl + o, sl + o);
        }
    };
    auto fillA = [&](int c) {
        int buf = c & 1;
        uint32_t d = sb + OFF_A + buf * 8192;
        const uint8_t* s = g_abf + ((size_t)(blockIdx.x * 16 + c)) * 8192;
        if (tid < 512) {
            int o = tid * 16;
            cp_async16(d + o, s + o);
        }
    };

    // preamble
    fillB(0); fillA(0); cp_commit();

    for (int c = 0; c < NCHUNK; ++c) {
        __syncthreads();                 // everyone done reading buffer (c+1)&1
        if (c + 1 < NCHUNK) { fillB(c + 1); fillA(c + 1); }
        cp_commit();
        cp_wait<1>();                    // group c complete
        __syncthreads();                 // all fills visible

        int buf = c & 1;
        uint32_t ah = sb + OFF_A + buf * 8192;
        uint32_t al = ah + 4096;
        uint32_t bh = sb + OFF_B + (buf * 2 + 0) * 16384 + bpanel;
        uint32_t bl = sb + OFF_B + (buf * 2 + 1) * 16384 + bpanel;

        #pragma unroll
        for (int ks = 0; ks < 4; ++ks) {
            const int kb = ks * 16;
            uint32_t Ah[4], Al[4], BhF[4], BlF[4];
            {
                uint32_t off = SW128((uint32_t)(arow * 128 + (kb + acolk) * 2));
                ldsm4(Ah, ah + off);
                ldsm4(Al, al + off);
            }
            {
                uint32_t off = SW128((uint32_t)((kb + brow) * 128 + bcol * 2));
                ldsm4t(BhF, bh + off);
                ldsm4t(BlF, bl + off);
            }
            // pass-major: hh (j0,j1), hl, lh — RAW chains broken
            #pragma unroll
            for (int j = 0; j < 2; ++j) mma16816(acc[j], Ah, BhF[j * 2], BhF[j * 2 + 1]);
            #pragma unroll
            for (int j = 0; j < 2; ++j) mma16816(acc[j], Ah, BlF[j * 2], BlF[j * 2 + 1]);
            #pragma unroll
            for (int j = 0; j < 2; ++j) mma16816(acc[j], Al, BhF[j * 2], BhF[j * 2 + 1]);
        }
    }
    __syncthreads();   // compute done before smem repurpose

    // ---- epilogue: fragments -> bias + tanh -> Hs; stage W2 into smem ----
    const int NO = half ? NL : NT;
    const float* W2 = half ? W2r : W2t;
    const float* b1 = half ? b1r : b1t;
    float* Hs  = (float*)(smem + OFF_HS);    // [32][HSS]
    float* W2s = (float*)(smem + OFF_W2S);   // [H_][NO]

    #pragma unroll
    for (int j = 0; j < 2; ++j) {
        int row = wm * 16 + (lane >> 2);
        int col = wn * 16 + j * 8 + (lane & 3) * 2;
        float bv0 = (col < H_)     ? __ldg(b1 + col)     : 0.f;
        float bv1 = (col + 1 < H_) ? __ldg(b1 + col + 1) : 0.f;
        Hs[row * HSS + col]           = tanhf(acc[j][0] + bv0);
        Hs[row * HSS + col + 1]       = tanhf(acc[j][1] + bv1);
        Hs[(row + 8) * HSS + col]     = tanhf(acc[j][2] + bv0);
        Hs[(row + 8) * HSS + col + 1] = tanhf(acc[j][3] + bv1);
    }
    for (int i = tid; i < H_ * NO; i += THREADS) W2s[i] = __ldg(W2 + i);
    __syncthreads();

    // ---- tiny layer 2 + final tanh (4-way partial sums) ----
    const float* b2 = half ? b2r : b2t;
    float* obase = half ? (out + B_TOT * NT) : out;

    for (int idx = tid; idx < BM * NO; idx += THREADS) {
        int row = idx / NO;
        int o   = idx - row * NO;
        const float* hrow = Hs + row * HSS;
        float s0 = 0.f, s1 = 0.f, s2 = 0.f, s3 = 0.f;
        #pragma unroll 4
        for (int k = 0; k < 124; k += 4) {
            s0 += hrow[k]     * W2s[k * NO + o];
            s1 += hrow[k + 1] * W2s[(k + 1) * NO + o];
            s2 += hrow[k + 2] * W2s[(k + 2) * NO + o];
            s3 += hrow[k + 3] * W2s[(k + 3) * NO + o];
        }
        float s = __ldg(b2 + o) + ((s0 + s1) + (s2 + s3))
                + hrow[124] * W2s[124 * NO + o];
        obase[(b0 + row) * NO + o] = tanhf(s);
    }
}

extern "C" void kernel_launch(void* const* d_in, const int* in_sizes, int n_in,
                              void* d_out, int out_size)
{
    const float* lstm_out     = (const float*)d_in[0];
    const int*   stack_index  = (const int*)  d_in[1];
    const int*   stack_len    = (const int*)  d_in[2];
    const int*   buffer_index = (const int*)  d_in[3];
    const int*   buffer_len   = (const int*)  d_in[4];
    const float* W1t          = (const float*)d_in[5];
    const float* b1t          = (const float*)d_in[6];
    const float* W2t          = (const float*)d_in[7];
    const float* b2t          = (const float*)d_in[8];
    const float* W1r          = (const float*)d_in[9];
    const float* b1r          = (const float*)d_in[10];
    const float* W2r          = (const float*)d_in[11];
    const float* b2r          = (const float*)d_in[12];
    float* out = (float*)d_out;

    prep_kernel<<<1536, 256>>>(W1t, W1r, lstm_out, stack_index, stack_len,
                               buffer_index, buffer_len);

    cudaFuncSetAttribute(parser_hmma_kernel,
                         cudaFuncAttributeMaxDynamicSharedMemorySize, SMEM_TOTAL);
    dim3 grid(B_TOT / BM, 2);
    parser_hmma_kernel<<<grid, THREADS, SMEM_TOTAL>>>(
        b1t, W2t, b2t, b1r, W2r, b2r, out);
}

// round 8
// speedup vs baseline: 1.3167x; 1.3167x over previous
#include <cuda_runtime.h>
#include <cuda_bf16.h>
#include <stdint.h>

// Problem constants
#define B_TOT   4096
#define T_      64
#define D_      250
#define K_      1000
#define H_      125
#define NT      4
#define NL      50

// Tiling
#define BM      32
#define BN      128
#define KCH     64
#define NCHUNK  16
#define THREADS 512
#define HSS     132

// smem layout (bytes)
#define OFF_A    0                    // [buf2][hi|lo 4096 each] -> 16384
#define OFF_B    16384                // [buf2][hi 16384 | lo 16384] -> 65536
#define OFF_SOFF 81920                // 32*4 ints
#define SMEM_TOTAL (81920 + 512)
#define OFF_HS   OFF_B                // epilogue: Hs[32][HSS] f32
#define OFF_W2S  (OFF_B + 16896)      // W2 cache (<= 25000 B)

#define SW128(x) ((x) ^ ((((uint32_t)(x)) >> 3) & 0x70))

// Pre-split, pre-swizzled W1 images: [half][hi/lo][chunk][16384B]
__device__ __align__(16) uint8_t g_wbf[(size_t)2 * 2 * 16 * 16384];

__device__ __forceinline__ uint32_t smem_u32(const void* p) {
    uint32_t a;
    asm("{ .reg .u64 t; cvta.to.shared.u64 t, %1; cvt.u32.u64 %0, t; }"
        : "=r"(a) : "l"(p));
    return a;
}
__device__ __forceinline__ void ldsm4(uint32_t r[4], uint32_t a) {
    asm volatile("ldmatrix.sync.aligned.m8n8.x4.shared.b16 {%0,%1,%2,%3}, [%4];"
        : "=r"(r[0]), "=r"(r[1]), "=r"(r[2]), "=r"(r[3]) : "r"(a));
}
__device__ __forceinline__ void ldsm4t(uint32_t r[4], uint32_t a) {
    asm volatile("ldmatrix.sync.aligned.m8n8.x4.trans.shared.b16 {%0,%1,%2,%3}, [%4];"
        : "=r"(r[0]), "=r"(r[1]), "=r"(r[2]), "=r"(r[3]) : "r"(a));
}
__device__ __forceinline__ void mma16816(float c[4], const uint32_t a[4],
                                         uint32_t b0, uint32_t b1) {
    asm volatile(
        "mma.sync.aligned.m16n8k16.row.col.f32.bf16.bf16.f32 "
        "{%0,%1,%2,%3}, {%4,%5,%6,%7}, {%8,%9}, {%0,%1,%2,%3};"
        : "+f"(c[0]), "+f"(c[1]), "+f"(c[2]), "+f"(c[3])
        : "r"(a[0]), "r"(a[1]), "r"(a[2]), "r"(a[3]), "r"(b0), "r"(b1));
}
__device__ __forceinline__ void cp_async16(uint32_t s, const void* g) {
    asm volatile("cp.async.cg.shared.global [%0], [%1], 16;" :: "r"(s), "l"(g) : "memory");
}
__device__ __forceinline__ void cp_commit() {
    asm volatile("cp.async.commit_group;" ::: "memory");
}
template <int N> __device__ __forceinline__ void cp_wait() {
    asm volatile("cp.async.wait_group %0;" :: "n"(N) : "memory");
}

// ------- prep W1 only: split into swizzled bf16 hi/lo chunk images -------
__global__ void prep_w_kernel(const float* __restrict__ W1t,
                              const float* __restrict__ W1r)
{
    int idx  = blockIdx.x * blockDim.x + threadIdx.x;   // 0..131071
    int np   = idx & 63;
    int k    = (idx >> 6) & 1023;
    int half = idx >> 16;
    const float* W1 = half ? W1r : W1t;

    int n0 = np * 2;
    float w0 = 0.f, w1 = 0.f;
    if (k < K_) {
        if (n0 < H_)     w0 = W1[k * H_ + n0];
        if (n0 + 1 < H_) w1 = W1[k * H_ + n0 + 1];
    }
    __nv_bfloat16 h0 = __float2bfloat16(w0);
    __nv_bfloat16 h1 = __float2bfloat16(w1);
    __nv_bfloat16 l0 = __float2bfloat16(w0 - __bfloat162float(h0));
    __nv_bfloat16 l1 = __float2bfloat16(w1 - __bfloat162float(h1));

    int chunk = k >> 6, kloc = k & 63;
    int panel = n0 >> 6, nloc = n0 & 63;
    uint32_t sw = SW128((uint32_t)(kloc * 128 + nloc * 2));
    size_t ohi = ((size_t)(half * 2 + 0) * 16 + chunk) * 16384 + panel * 8192 + sw;
    size_t olo = ((size_t)(half * 2 + 1) * 16 + chunk) * 16384 + panel * 8192 + sw;

    *(__nv_bfloat162*)(g_wbf + ohi) = __halves2bfloat162(h0, h1);
    *(__nv_bfloat162*)(g_wbf + olo) = __halves2bfloat162(l0, l1);
}

// ---------------- main kernel: 512 threads, warp tile 16x16, A reg-prefetch ----
__global__ __launch_bounds__(THREADS, 2)
void parser_hmma_kernel(const float* __restrict__ lstm_out,
                        const int*   __restrict__ stack_index,
                        const int*   __restrict__ stack_len,
                        const int*   __restrict__ buffer_index,
                        const int*   __restrict__ buffer_len,
                        const float* __restrict__ b1t,
                        const float* __restrict__ W2t,
                        const float* __restrict__ b2t,
                        const float* __restrict__ b1r,
                        const float* __restrict__ W2r,
                        const float* __restrict__ b2r,
                        float* __restrict__ out)
{
    extern __shared__ char smem[];
    const uint32_t sb = smem_u32(smem);
    const int tid  = threadIdx.x;
    const int wid  = tid >> 5;
    const int lane = tid & 31;
    const int wm   = wid & 1;
    const int wn   = wid >> 1;
    const int b0   = blockIdx.x * BM;
    const int half = blockIdx.y;

    int* soff = (int*)(smem + OFF_SOFF);
    if (tid < BM * 4) {
        int row = tid >> 2, s = tid & 3;
        int b = b0 + row;
        int t, valid;
        if (s < 3) { valid = (s < stack_len[b]);  t = stack_index[b * 3 + s]; }
        else       { valid = (0 < buffer_len[b]); t = buffer_index[b]; }
        soff[tid] = valid ? (b * T_ + t) * D_ : -1;
    }
    __syncthreads();

    // A-gather geometry: 2 items/thread, item = it*512 + tid -> (m, kp)
    const int kp0 = tid & 31,        m0 = tid >> 5;          // item 0
    const int kp1 = (tid + 512) & 31, m1 = (tid + 512) >> 5; // item 1

    // ldmatrix geometry
    const int g = lane >> 3, r8 = lane & 7;
    const int arow  = wm * 16 + (g & 1) * 8 + r8;
    const int acolk = (g >> 1) * 8;
    const int brow  = (g & 1) * 8 + r8;
    const int bcol  = ((wn * 16) & 63) + (g >> 1) * 8;
    const uint32_t bpanel = (uint32_t)(wn >> 2) * 8192;

    float acc[2][4];
    #pragma unroll
    for (int j = 0; j < 2; ++j)
        #pragma unroll
        for (int e = 0; e < 4; ++e) acc[j][e] = 0.f;

    auto loadA = [&](int c, float2 rv[2]) {
        #pragma unroll
        for (int it = 0; it < 2; ++it) {
            int kp = it ? kp1 : kp0;
            int m  = it ? m1  : m0;
            int k  = c * KCH + 2 * kp;
            float2 v = make_float2(0.f, 0.f);
            if (k < K_) {
                int slot = k / D_;
                int d    = k - slot * D_;
                int off  = soff[m * 4 + slot];
                if (off >= 0) v = *(const float2*)(lstm_out + off + d);
            }
            rv[it] = v;
        }
    };
    auto storeA = [&](int c, const float2 rv[2]) {
        char* ah = smem + OFF_A + (c & 1) * 8192;
        char* al = ah + 4096;
        #pragma unroll
        for (int it = 0; it < 2; ++it) {
            int kp = it ? kp1 : kp0;
            int m  = it ? m1  : m0;
            float2 v = rv[it];
            __nv_bfloat16 hx = __float2bfloat16(v.x);
            __nv_bfloat16 hy = __float2bfloat16(v.y);
            __nv_bfloat16 lx = __float2bfloat16(v.x - __bfloat162float(hx));
            __nv_bfloat16 ly = __float2bfloat16(v.y - __bfloat162float(hy));
            uint32_t sw = SW128((uint32_t)(m * 128 + kp * 4));
            *(__nv_bfloat162*)(ah + sw) = __halves2bfloat162(hx, hy);
            *(__nv_bfloat162*)(al + sw) = __halves2bfloat162(lx, ly);
        }
    };
    auto fillB = [&](int c) {
        int buf = c & 1;
        uint32_t dh = sb + OFF_B + (buf * 2 + 0) * 16384;
        uint32_t dl = sb + OFF_B + (buf * 2 + 1) * 16384;
        const uint8_t* sh = g_wbf + ((size_t)(half * 2 + 0) * 16 + c) * 16384;
        const uint8_t* sl = g_wbf + ((size_t)(half * 2 + 1) * 16 + c) * 16384;
        #pragma unroll
        for (int it = 0; it < 2; ++it) {
            int o = (it * THREADS + tid) * 16;
            cp_async16(dh + o, sh + o);
            cp_async16(dl + o, sl + o);
        }
    };

    // prologue: B(0) async, A(0) to regs
    float2 rv[2], rv2[2];
    fillB(0); cp_commit();
    loadA(0, rv);

    for (int c = 0; c < NCHUNK; ++c) {
        __syncthreads();                     // buffers (c&1) free
        storeA(c, rv);                       // convert+store A(c)
        if (c + 1 < NCHUNK) {
            fillB(c + 1); cp_commit();
            loadA(c + 1, rv2);               // LDG issues now, consumed next iter
            cp_wait<1>();                    // B(c) arrived
        } else {
            cp_wait<0>();
        }
        __syncthreads();                     // A stores + B fills visible

        int buf = c & 1;
        uint32_t ah = sb + OFF_A + buf * 8192;
        uint32_t al = ah + 4096;
        uint32_t bh = sb + OFF_B + (buf * 2 + 0) * 16384 + bpanel;
        uint32_t bl = sb + OFF_B + (buf * 2 + 1) * 16384 + bpanel;

        #pragma unroll
        for (int ks = 0; ks < 4; ++ks) {
            const int kb = ks * 16;
            uint32_t Ah[4], Al[4], BhF[4], BlF[4];
            {
                uint32_t off = SW128((uint32_t)(arow * 128 + (kb + acolk) * 2));
                ldsm4(Ah, ah + off);
                ldsm4(Al, al + off);
            }
            {
                uint32_t off = SW128((uint32_t)((kb + brow) * 128 + bcol * 2));
                ldsm4t(BhF, bh + off);
                ldsm4t(BlF, bl + off);
            }
            #pragma unroll
            for (int j = 0; j < 2; ++j) mma16816(acc[j], Ah, BhF[j * 2], BhF[j * 2 + 1]);
            #pragma unroll
            for (int j = 0; j < 2; ++j) mma16816(acc[j], Ah, BlF[j * 2], BlF[j * 2 + 1]);
            #pragma unroll
            for (int j = 0; j < 2; ++j) mma16816(acc[j], Al, BhF[j * 2], BhF[j * 2 + 1]);
        }
        rv[0] = rv2[0]; rv[1] = rv2[1];
    }
    __syncthreads();

    // ---- epilogue: fragments -> bias + tanh -> Hs; stage W2 into smem ----
    const int NO = half ? NL : NT;
    const float* W2 = half ? W2r : W2t;
    const float* b1 = half ? b1r : b1t;
    float* Hs  = (float*)(smem + OFF_HS);
    float* W2s = (float*)(smem + OFF_W2S);

    #pragma unroll
    for (int j = 0; j < 2; ++j) {
        int row = wm * 16 + (lane >> 2);
        int col = wn * 16 + j * 8 + (lane & 3) * 2;
        float bv0 = (col < H_)     ? __ldg(b1 + col)     : 0.f;
        float bv1 = (col + 1 < H_) ? __ldg(b1 + col + 1) : 0.f;
        Hs[row * HSS + col]           = tanhf(acc[j][0] + bv0);
        Hs[row * HSS + col + 1]       = tanhf(acc[j][1] + bv1);
        Hs[(row + 8) * HSS + col]     = tanhf(acc[j][2] + bv0);
        Hs[(row + 8) * HSS + col + 1] = tanhf(acc[j][3] + bv1);
    }
    for (int i = tid; i < H_ * NO; i += THREADS) W2s[i] = __ldg(W2 + i);
    __syncthreads();

    // ---- tiny layer 2 + final tanh ----
    const float* b2 = half ? b2r : b2t;
    float* obase = half ? (out + B_TOT * NT) : out;

    for (int idx = tid; idx < BM * NO; idx += THREADS) {
        int row = idx / NO;
        int o   = idx - row * NO;
        const float* hrow = Hs + row * HSS;
        float s0 = 0.f, s1 = 0.f, s2 = 0.f, s3 = 0.f;
        #pragma unroll 4
        for (int k = 0; k < 124; k += 4) {
            s0 += hrow[k]     * W2s[k * NO + o];
            s1 += hrow[k + 1] * W2s[(k + 1) * NO + o];
            s2 += hrow[k + 2] * W2s[(k + 2) * NO + o];
            s3 += hrow[k + 3] * W2s[(k + 3) * NO + o];
        }
        float s = __ldg(b2 + o) + ((s0 + s1) + (s2 + s3))
                + hrow[124] * W2s[124 * NO + o];
        obase[(b0 + row) * NO + o] = tanhf(s);
    }
}

extern "C" void kernel_launch(void* const* d_in, const int* in_sizes, int n_in,
                              void* d_out, int out_size)
{
    const float* lstm_out     = (const float*)d_in[0];
    const int*   stack_index  = (const int*)  d_in[1];
    const int*   stack_len    = (const int*)  d_in[2];
    const int*   buffer_index = (const int*)  d_in[3];
    const int*   buffer_len   = (const int*)  d_in[4];
    const float* W1t          = (const float*)d_in[5];
    const float* b1t          = (const float*)d_in[6];
    const float* W2t          = (const float*)d_in[7];
    const float* b2t          = (const float*)d_in[8];
    const float* W1r          = (const float*)d_in[9];
    const float* b1r          = (const float*)d_in[10];
    const float* W2r          = (const float*)d_in[11];
    const float* b2r          = (const float*)d_in[12];
    float* out = (float*)d_out;

    prep_w_kernel<<<512, 256>>>(W1t, W1r);

    cudaFuncSetAttribute(parser_hmma_kernel,
                         cudaFuncAttributeMaxDynamicSharedMemorySize, SMEM_TOTAL);
    dim3 grid(B_TOT / BM, 2);
    parser_hmma_kernel<<<grid, THREADS, SMEM_TOTAL>>>(
        lstm_out, stack_index, stack_len, buffer_index, buffer_len,
        b1t, W2t, b2t, b1r, W2r, b2r, out);
}

// round 9
// speedup vs baseline: 1.3504x; 1.0256x over previous
#include <cuda_runtime.h>
#include <cuda_bf16.h>
#include <stdint.h>

// Problem constants
#define B_TOT   4096
#define T_      64
#define D_      250
#define K_      1000
#define H_      125
#define NT      4
#define NL      50

// Tiling
#define BM      32
#define BN      128
#define KCH     64
#define NCHUNK  16
#define THREADS 512
#define HSS     132

// smem layout (bytes)
#define OFF_A    0                    // [buf2][hi|lo 4096 each] -> 16384
#define OFF_B    16384                // [buf2][hi 16384 | lo 16384] -> 65536
#define OFF_SOFF 81920                // 32*4 ints
#define SMEM_TOTAL (81920 + 512)
#define OFF_HS   OFF_B                // epilogue: Hs[32][HSS] f32
#define OFF_W2S  (OFF_B + 16896)      // W2 cache (<= 25000 B)

#define SW128(x) ((x) ^ ((((uint32_t)(x)) >> 3) & 0x70))

// Pre-split, pre-swizzled W1 images: [half][hi/lo][chunk][16384B]
__device__ __align__(16) uint8_t g_wbf[(size_t)2 * 2 * 16 * 16384];

__device__ __forceinline__ uint32_t smem_u32(const void* p) {
    uint32_t a;
    asm("{ .reg .u64 t; cvta.to.shared.u64 t, %1; cvt.u32.u64 %0, t; }"
        : "=r"(a) : "l"(p));
    return a;
}
__device__ __forceinline__ void ldsm4(uint32_t r[4], uint32_t a) {
    asm volatile("ldmatrix.sync.aligned.m8n8.x4.shared.b16 {%0,%1,%2,%3}, [%4];"
        : "=r"(r[0]), "=r"(r[1]), "=r"(r[2]), "=r"(r[3]) : "r"(a));
}
__device__ __forceinline__ void ldsm4t(uint32_t r[4], uint32_t a) {
    asm volatile("ldmatrix.sync.aligned.m8n8.x4.trans.shared.b16 {%0,%1,%2,%3}, [%4];"
        : "=r"(r[0]), "=r"(r[1]), "=r"(r[2]), "=r"(r[3]) : "r"(a));
}
__device__ __forceinline__ void mma16816(float c[4], const uint32_t a[4],
                                         uint32_t b0, uint32_t b1) {
    asm volatile(
        "mma.sync.aligned.m16n8k16.row.col.f32.bf16.bf16.f32 "
        "{%0,%1,%2,%3}, {%4,%5,%6,%7}, {%8,%9}, {%0,%1,%2,%3};"
        : "+f"(c[0]), "+f"(c[1]), "+f"(c[2]), "+f"(c[3])
        : "r"(a[0]), "r"(a[1]), "r"(a[2]), "r"(a[3]), "r"(b0), "r"(b1));
}
__device__ __forceinline__ void cp_async16(uint32_t s, const void* g) {
    asm volatile("cp.async.cg.shared.global [%0], [%1], 16;" :: "r"(s), "l"(g) : "memory");
}
__device__ __forceinline__ void cp_commit() {
    asm volatile("cp.async.commit_group;" ::: "memory");
}
template <int N> __device__ __forceinline__ void cp_wait() {
    asm volatile("cp.async.wait_group %0;" :: "n"(N) : "memory");
}

// ------- prep W1 only: split into swizzled bf16 hi/lo chunk images -------
__global__ void prep_w_kernel(const float* __restrict__ W1t,
                              const float* __restrict__ W1r)
{
    int idx  = blockIdx.x * blockDim.x + threadIdx.x;   // 0..131071
    int np   = idx & 63;
    int k    = (idx >> 6) & 1023;
    int half = idx >> 16;
    const float* W1 = half ? W1r : W1t;

    int n0 = np * 2;
    float w0 = 0.f, w1 = 0.f;
    if (k < K_) {
        if (n0 < H_)     w0 = W1[k * H_ + n0];
        if (n0 + 1 < H_) w1 = W1[k * H_ + n0 + 1];
    }
    __nv_bfloat16 h0 = __float2bfloat16(w0);
    __nv_bfloat16 h1 = __float2bfloat16(w1);
    __nv_bfloat16 l0 = __float2bfloat16(w0 - __bfloat162float(h0));
    __nv_bfloat16 l1 = __float2bfloat16(w1 - __bfloat162float(h1));

    int chunk = k >> 6, kloc = k & 63;
    int panel = n0 >> 6, nloc = n0 & 63;
    uint32_t sw = SW128((uint32_t)(kloc * 128 + nloc * 2));
    size_t ohi = ((size_t)(half * 2 + 0) * 16 + chunk) * 16384 + panel * 8192 + sw;
    size_t olo = ((size_t)(half * 2 + 1) * 16 + chunk) * 16384 + panel * 8192 + sw;

    *(__nv_bfloat162*)(g_wbf + ohi) = __halves2bfloat162(h0, h1);
    *(__nv_bfloat162*)(g_wbf + olo) = __halves2bfloat162(l0, l1);
}

// ------ main kernel: 512 threads, warp tile 16x16, A reg-prefetch depth 2 ------
__global__ __launch_bounds__(THREADS, 2)
void parser_hmma_kernel(const float* __restrict__ lstm_out,
                        const int*   __restrict__ stack_index,
                        const int*   __restrict__ stack_len,
                        const int*   __restrict__ buffer_index,
                        const int*   __restrict__ buffer_len,
                        const float* __restrict__ b1t,
                        const float* __restrict__ W2t,
                        const float* __restrict__ b2t,
                        const float* __restrict__ b1r,
                        const float* __restrict__ W2r,
                        const float* __restrict__ b2r,
                        float* __restrict__ out)
{
    extern __shared__ char smem[];
    const uint32_t sb = smem_u32(smem);
    const int tid  = threadIdx.x;
    const int wid  = tid >> 5;
    const int lane = tid & 31;
    const int wm   = wid & 1;
    const int wn   = wid >> 1;
    const int b0   = blockIdx.x * BM;
    const int half = blockIdx.y;

    int* soff = (int*)(smem + OFF_SOFF);
    if (tid < BM * 4) {
        int row = tid >> 2, s = tid & 3;
        int b = b0 + row;
        int t, valid;
        if (s < 3) { valid = (s < stack_len[b]);  t = stack_index[b * 3 + s]; }
        else       { valid = (0 < buffer_len[b]); t = buffer_index[b]; }
        soff[tid] = valid ? (b * T_ + t) * D_ : -1;
    }
    __syncthreads();

    // A-gather geometry: 2 items/thread, item = it*512 + tid -> (m, kp)
    const int kp0 = tid & 31,         m0 = tid >> 5;
    const int kp1 = (tid + 512) & 31, m1 = (tid + 512) >> 5;
    const uint32_t swst0 = SW128((uint32_t)(m0 * 128 + kp0 * 4));   // store addr, chunk-invariant
    const uint32_t swst1 = SW128((uint32_t)(m1 * 128 + kp1 * 4));

    // ldmatrix geometry
    const int g = lane >> 3, r8 = lane & 7;
    const int arow  = wm * 16 + (g & 1) * 8 + r8;
    const int acolk = (g >> 1) * 8;
    const int brow  = (g & 1) * 8 + r8;
    const int bcol  = ((wn * 16) & 63) + (g >> 1) * 8;
    const uint32_t bpanel = (uint32_t)(wn >> 2) * 8192;

    float acc[2][4];
    #pragma unroll
    for (int j = 0; j < 2; ++j)
        #pragma unroll
        for (int e = 0; e < 4; ++e) acc[j][e] = 0.f;

    auto loadA = [&](int c, float2 (&rv)[2]) {
        #pragma unroll
        for (int it = 0; it < 2; ++it) {
            int kp = it ? kp1 : kp0;
            int m  = it ? m1  : m0;
            int k  = c * KCH + 2 * kp;
            float2 v = make_float2(0.f, 0.f);
            if (k < K_) {
                int slot = k / D_;
                int d    = k - slot * D_;
                int off  = soff[m * 4 + slot];
                if (off >= 0) v = *(const float2*)(lstm_out + off + d);
            }
            rv[it] = v;
        }
    };
    auto storeA = [&](int c, const float2 (&rv)[2]) {
        char* ah = smem + OFF_A + (c & 1) * 8192;
        char* al = ah + 4096;
        #pragma unroll
        for (int it = 0; it < 2; ++it) {
            float2 v = rv[it];
            __nv_bfloat16 hx = __float2bfloat16(v.x);
            __nv_bfloat16 hy = __float2bfloat16(v.y);
            __nv_bfloat16 lx = __float2bfloat16(v.x - __bfloat162float(hx));
            __nv_bfloat16 ly = __float2bfloat16(v.y - __bfloat162float(hy));
            uint32_t sw = it ? swst1 : swst0;
            *(__nv_bfloat162*)(ah + sw) = __halves2bfloat162(hx, hy);
            *(__nv_bfloat162*)(al + sw) = __halves2bfloat162(lx, ly);
        }
    };
    auto fillB = [&](int c) {
        int buf = c & 1;
        uint32_t dh = sb + OFF_B + (buf * 2 + 0) * 16384;
        uint32_t dl = sb + OFF_B + (buf * 2 + 1) * 16384;
        const uint8_t* sh = g_wbf + ((size_t)(half * 2 + 0) * 16 + c) * 16384;
        const uint8_t* sl = g_wbf + ((size_t)(half * 2 + 1) * 16 + c) * 16384;
        #pragma unroll
        for (int it = 0; it < 2; ++it) {
            int o = (it * THREADS + tid) * 16;
            cp_async16(dh + o, sh + o);
            cp_async16(dl + o, sl + o);
        }
    };

    // prologue: B(0) async; A(0), A(1) to regs (depth-2 prefetch)
    float2 rva[2], rvb[2];
    fillB(0); cp_commit();
    loadA(0, rva);
    loadA(1, rvb);

    #pragma unroll 2
    for (int c = 0; c < NCHUNK; ++c) {
        float2 (&rvc)[2] = (c & 1) ? rvb : rva;
        // A buffer parity c&1 is free (its last readers finished before the
        // barriers of iteration c-1) -> storeA overlaps warp skew, before S1.
        storeA(c, rvc);
        if (c + 2 < NCHUNK) loadA(c + 2, rvc);   // LDG covered by ~2 compute phases

        __syncthreads();                          // S1: B buffer (c+1)&1 free
        if (c + 1 < NCHUNK) {
            fillB(c + 1); cp_commit();
            cp_wait<1>();                         // B(c) arrived
        } else {
            cp_wait<0>();
        }
        __syncthreads();                          // S2: A stores + B fills visible

        int buf = c & 1;
        uint32_t ah = sb + OFF_A + buf * 8192;
        uint32_t al = ah + 4096;
        uint32_t bh = sb + OFF_B + (buf * 2 + 0) * 16384 + bpanel;
        uint32_t bl = sb + OFF_B + (buf * 2 + 1) * 16384 + bpanel;

        #pragma unroll
        for (int ks = 0; ks < 4; ++ks) {
            const int kb = ks * 16;
            uint32_t Ah[4], Al[4], BhF[4], BlF[4];
            {
                uint32_t off = SW128((uint32_t)(arow * 128 + (kb + acolk) * 2));
                ldsm4(Ah, ah + off);
                ldsm4(Al, al + off);
            }
            {
                uint32_t off = SW128((uint32_t)((kb + brow) * 128 + bcol * 2));
                ldsm4t(BhF, bh + off);
                ldsm4t(BlF, bl + off);
            }
            #pragma unroll
            for (int j = 0; j < 2; ++j) mma16816(acc[j], Ah, BhF[j * 2], BhF[j * 2 + 1]);
            #pragma unroll
            for (int j = 0; j < 2; ++j) mma16816(acc[j], Ah, BlF[j * 2], BlF[j * 2 + 1]);
            #pragma unroll
            for (int j = 0; j < 2; ++j) mma16816(acc[j], Al, BhF[j * 2], BhF[j * 2 + 1]);
        }
    }
    __syncthreads();

    // ---- epilogue: fragments -> bias + tanh -> Hs; stage W2 into smem ----
    const int NO = half ? NL : NT;
    const float* W2 = half ? W2r : W2t;
    const float* b1 = half ? b1r : b1t;
    float* Hs  = (float*)(smem + OFF_HS);
    float* W2s = (float*)(smem + OFF_W2S);

    #pragma unroll
    for (int j = 0; j < 2; ++j) {
        int row = wm * 16 + (lane >> 2);
        int col = wn * 16 + j * 8 + (lane & 3) * 2;
        float bv0 = (col < H_)     ? __ldg(b1 + col)     : 0.f;
        float bv1 = (col + 1 < H_) ? __ldg(b1 + col + 1) : 0.f;
        Hs[row * HSS + col]           = tanhf(acc[j][0] + bv0);
        Hs[row * HSS + col + 1]       = tanhf(acc[j][1] + bv1);
        Hs[(row + 8) * HSS + col]     = tanhf(acc[j][2] + bv0);
        Hs[(row + 8) * HSS + col + 1] = tanhf(acc[j][3] + bv1);
    }
    for (int i = tid; i < H_ * NO; i += THREADS) W2s[i] = __ldg(W2 + i);
    __syncthreads();

    // ---- tiny layer 2 + final tanh ----
    const float* b2 = half ? b2r : b2t;
    float* obase = half ? (out + B_TOT * NT) : out;

    for (int idx = tid; idx < BM * NO; idx += THREADS) {
        int row = idx / NO;
        int o   = idx - row * NO;
        const float* hrow = Hs + row * HSS;
        float s0 = 0.f, s1 = 0.f, s2 = 0.f, s3 = 0.f;
        #pragma unroll 4
        for (int k = 0; k < 124; k += 4) {
            s0 += hrow[k]     * W2s[k * NO + o];
            s1 += hrow[k + 1] * W2s[(k + 1) * NO + o];
            s2 += hrow[k + 2] * W2s[(k + 2) * NO + o];
            s3 += hrow[k + 3] * W2s[(k + 3) * NO + o];
        }
        float s = __ldg(b2 + o) + ((s0 + s1) + (s2 + s3))
                + hrow[124] * W2s[124 * NO + o];
        obase[(b0 + row) * NO + o] = tanhf(s);
    }
}

extern "C" void kernel_launch(void* const* d_in, const int* in_sizes, int n_in,
                              void* d_out, int out_size)
{
    const float* lstm_out     = (const float*)d_in[0];
    const int*   stack_index  = (const int*)  d_in[1];
    const int*   stack_len    = (const int*)  d_in[2];
    const int*   buffer_index = (const int*)  d_in[3];
    const int*   buffer_len   = (const int*)  d_in[4];
    const float* W1t          = (const float*)d_in[5];
    const float* b1t          = (const float*)d_in[6];
    const float* W2t          = (const float*)d_in[7];
    const float* b2t          = (const float*)d_in[8];
    const float* W1r          = (const float*)d_in[9];
    const float* b1r          = (const float*)d_in[10];
    const float* W2r          = (const float*)d_in[11];
    const float* b2r          = (const float*)d_in[12];
    float* out = (float*)d_out;

    prep_w_kernel<<<512, 256>>>(W1t, W1r);

    cudaFuncSetAttribute(parser_hmma_kernel,
                         cudaFuncAttributeMaxDynamicSharedMemorySize, SMEM_TOTAL);
    dim3 grid(B_TOT / BM, 2);
    parser_hmma_kernel<<<grid, THREADS, SMEM_TOTAL>>>(
        lstm_out, stack_index, stack_len, buffer_index, buffer_len,
        b1t, W2t, b2t, b1r, W2r, b2r, out);
}

// round 10
// speedup vs baseline: 1.3657x; 1.0113x over previous
#include <cuda_runtime.h>
#include <cuda_bf16.h>
#include <stdint.h>

// Problem constants
#define B_TOT   4096
#define T_      64
#define D_      250
#define K_      1000
#define H_      125
#define NT      4
#define NL      50

// Tiling
#define BM      32
#define BN      128
#define KCH     64
#define NCHUNK  16
#define THREADS 512
#define HSS     132

// smem layout (bytes)
#define OFF_A    0                    // [buf2][hi|lo 4096 each] -> 16384
#define OFF_B    16384                // [buf2][hi 16384 | lo 16384] -> 65536
#define OFF_SOFF 81920                // 32*4 ints
#define SMEM_TOTAL (81920 + 512)
#define OFF_RS   OFF_A                // k-split reduction buffer: 8*32*16*4 = 16384
#define OFF_HS   OFF_B                // epilogue: Hs[32][HSS] f32
#define OFF_W2S  (OFF_B + 16896)      // W2 cache (<= 25000 B)

#define SW128(x) ((x) ^ ((((uint32_t)(x)) >> 3) & 0x70))

// Pre-split, pre-swizzled W1 images: [half][hi/lo][chunk][16384B]
__device__ __align__(16) uint8_t g_wbf[(size_t)2 * 2 * 16 * 16384];

__device__ __forceinline__ uint32_t smem_u32(const void* p) {
    uint32_t a;
    asm("{ .reg .u64 t; cvta.to.shared.u64 t, %1; cvt.u32.u64 %0, t; }"
        : "=r"(a) : "l"(p));
    return a;
}
__device__ __forceinline__ void ldsm4(uint32_t r[4], uint32_t a) {
    asm volatile("ldmatrix.sync.aligned.m8n8.x4.shared.b16 {%0,%1,%2,%3}, [%4];"
        : "=r"(r[0]), "=r"(r[1]), "=r"(r[2]), "=r"(r[3]) : "r"(a));
}
__device__ __forceinline__ void ldsm4t(uint32_t r[4], uint32_t a) {
    asm volatile("ldmatrix.sync.aligned.m8n8.x4.trans.shared.b16 {%0,%1,%2,%3}, [%4];"
        : "=r"(r[0]), "=r"(r[1]), "=r"(r[2]), "=r"(r[3]) : "r"(a));
}
__device__ __forceinline__ void mma16816(float c[4], const uint32_t a[4],
                                         uint32_t b0, uint32_t b1) {
    asm volatile(
        "mma.sync.aligned.m16n8k16.row.col.f32.bf16.bf16.f32 "
        "{%0,%1,%2,%3}, {%4,%5,%6,%7}, {%8,%9}, {%0,%1,%2,%3};"
        : "+f"(c[0]), "+f"(c[1]), "+f"(c[2]), "+f"(c[3])
        : "r"(a[0]), "r"(a[1]), "r"(a[2]), "r"(a[3]), "r"(b0), "r"(b1));
}
__device__ __forceinline__ void cp_async16(uint32_t s, const void* g) {
    asm volatile("cp.async.cg.shared.global [%0], [%1], 16;" :: "r"(s), "l"(g) : "memory");
}
__device__ __forceinline__ void cp_commit() {
    asm volatile("cp.async.commit_group;" ::: "memory");
}
template <int N> __device__ __forceinline__ void cp_wait() {
    asm volatile("cp.async.wait_group %0;" :: "n"(N) : "memory");
}

// ------- prep W1 only: split into swizzled bf16 hi/lo chunk images -------
__global__ void prep_w_kernel(const float* __restrict__ W1t,
                              const float* __restrict__ W1r)
{
    int idx  = blockIdx.x * blockDim.x + threadIdx.x;   // 0..131071
    int np   = idx & 63;
    int k    = (idx >> 6) & 1023;
    int half = idx >> 16;
    const float* W1 = half ? W1r : W1t;

    int n0 = np * 2;
    float w0 = 0.f, w1 = 0.f;
    if (k < K_) {
        if (n0 < H_)     w0 = W1[k * H_ + n0];
        if (n0 + 1 < H_) w1 = W1[k * H_ + n0 + 1];
    }
    __nv_bfloat16 h0 = __float2bfloat16(w0);
    __nv_bfloat16 h1 = __float2bfloat16(w1);
    __nv_bfloat16 l0 = __float2bfloat16(w0 - __bfloat162float(h0));
    __nv_bfloat16 l1 = __float2bfloat16(w1 - __bfloat162float(h1));

    int chunk = k >> 6, kloc = k & 63;
    int panel = n0 >> 6, nloc = n0 & 63;
    uint32_t sw = SW128((uint32_t)(kloc * 128 + nloc * 2));
    size_t ohi = ((size_t)(half * 2 + 0) * 16 + chunk) * 16384 + panel * 8192 + sw;
    size_t olo = ((size_t)(half * 2 + 1) * 16 + chunk) * 16384 + panel * 8192 + sw;

    *(__nv_bfloat162*)(g_wbf + ohi) = __halves2bfloat162(h0, h1);
    *(__nv_bfloat162*)(g_wbf + olo) = __halves2bfloat162(l0, l1);
}

// -- main: 512 thr, warps = 2(M) x 4(N) x 2(Ksplit), warp tile 16x32, A prefetch 2 --
__global__ __launch_bounds__(THREADS, 2)
void parser_hmma_kernel(const float* __restrict__ lstm_out,
                        const int*   __restrict__ stack_index,
                        const int*   __restrict__ stack_len,
                        const int*   __restrict__ buffer_index,
                        const int*   __restrict__ buffer_len,
                        const float* __restrict__ b1t,
                        const float* __restrict__ W2t,
                        const float* __restrict__ b2t,
                        const float* __restrict__ b1r,
                        const float* __restrict__ W2r,
                        const float* __restrict__ b2r,
                        float* __restrict__ out)
{
    extern __shared__ char smem[];
    const uint32_t sb = smem_u32(smem);
    const int tid  = threadIdx.x;
    const int wid  = tid >> 5;
    const int lane = tid & 31;
    const int ksp  = wid & 1;          // K-split: ks = ksp*2 + {0,1}
    const int wm   = (wid >> 1) & 1;   // M group: rows wm*16..+15
    const int wn   = wid >> 2;         // N group (0..3): cols wn*32..+31
    const int b0   = blockIdx.x * BM;
    const int half = blockIdx.y;

    int* soff = (int*)(smem + OFF_SOFF);
    if (tid < BM * 4) {
        int row = tid >> 2, s = tid & 3;
        int b = b0 + row;
        int t, valid;
        if (s < 3) { valid = (s < stack_len[b]);  t = stack_index[b * 3 + s]; }
        else       { valid = (0 < buffer_len[b]); t = buffer_index[b]; }
        soff[tid] = valid ? (b * T_ + t) * D_ : -1;
    }
    __syncthreads();

    // A-gather geometry: 2 items/thread
    const int kp0 = tid & 31,         m0 = tid >> 5;
    const int kp1 = (tid + 512) & 31, m1 = (tid + 512) >> 5;
    const uint32_t swst0 = SW128((uint32_t)(m0 * 128 + kp0 * 4));
    const uint32_t swst1 = SW128((uint32_t)(m1 * 128 + kp1 * 4));

    // ldmatrix geometry (chunk-invariant offsets, 2 kk steps each)
    const int g = lane >> 3, r8 = lane & 7;
    const int arow = wm * 16 + (g & 1) * 8 + r8;
    const int acol = (g >> 1) * 8;
    const int brow = (g & 1) * 8 + r8;
    const int bc0  = ((wn * 32) & 63) + (g >> 1) * 8;   // first 16-col group
    const uint32_t bpanel = (uint32_t)(wn >> 1) * 8192;

    uint32_t aoff[2], boff0[2], boff1[2];
    #pragma unroll
    for (int kk = 0; kk < 2; ++kk) {
        int kb = (ksp * 2 + kk) * 16;
        aoff[kk]  = SW128((uint32_t)(arow * 128 + (kb + acol) * 2));
        boff0[kk] = SW128((uint32_t)((kb + brow) * 128 + bc0 * 2));
        boff1[kk] = SW128((uint32_t)((kb + brow) * 128 + (bc0 + 16) * 2));
    }

    float acc[4][4];
    #pragma unroll
    for (int j = 0; j < 4; ++j)
        #pragma unroll
        for (int e = 0; e < 4; ++e) acc[j][e] = 0.f;

    auto loadA = [&](int c, float2 (&rv)[2]) {
        #pragma unroll
        for (int it = 0; it < 2; ++it) {
            int kp = it ? kp1 : kp0;
            int m  = it ? m1  : m0;
            int k  = c * KCH + 2 * kp;
            float2 v = make_float2(0.f, 0.f);
            if (k < K_) {
                int slot = k / D_;
                int d    = k - slot * D_;
                int off  = soff[m * 4 + slot];
                if (off >= 0) v = *(const float2*)(lstm_out + off + d);
            }
            rv[it] = v;
        }
    };
    auto storeA = [&](int c, const float2 (&rv)[2]) {
        char* ah = smem + OFF_A + (c & 1) * 8192;
        char* al = ah + 4096;
        #pragma unroll
        for (int it = 0; it < 2; ++it) {
            float2 v = rv[it];
            __nv_bfloat16 hx = __float2bfloat16(v.x);
            __nv_bfloat16 hy = __float2bfloat16(v.y);
            __nv_bfloat16 lx = __float2bfloat16(v.x - __bfloat162float(hx));
            __nv_bfloat16 ly = __float2bfloat16(v.y - __bfloat162float(hy));
            uint32_t sw = it ? swst1 : swst0;
            *(__nv_bfloat162*)(ah + sw) = __halves2bfloat162(hx, hy);
            *(__nv_bfloat162*)(al + sw) = __halves2bfloat162(lx, ly);
        }
    };
    auto fillB = [&](int c) {
        int buf = c & 1;
        uint32_t dh = sb + OFF_B + (buf * 2 + 0) * 16384;
        uint32_t dl = sb + OFF_B + (buf * 2 + 1) * 16384;
        const uint8_t* sh = g_wbf + ((size_t)(half * 2 + 0) * 16 + c) * 16384;
        const uint8_t* sl = g_wbf + ((size_t)(half * 2 + 1) * 16 + c) * 16384;
        #pragma unroll
        for (int it = 0; it < 2; ++it) {
            int o = (it * THREADS + tid) * 16;
            cp_async16(dh + o, sh + o);
            cp_async16(dl + o, sl + o);
        }
    };

    // prologue
    float2 rva[2], rvb[2];
    fillB(0); cp_commit();
    loadA(0, rva);
    loadA(1, rvb);

    #pragma unroll 2
    for (int c = 0; c < NCHUNK; ++c) {
        float2 (&rvc)[2] = (c & 1) ? rvb : rva;
        storeA(c, rvc);
        if (c + 2 < NCHUNK) loadA(c + 2, rvc);

        __syncthreads();                 // S1: B buffer (c+1)&1 free
        if (c + 1 < NCHUNK) {
            fillB(c + 1); cp_commit();
            cp_wait<1>();
        } else {
            cp_wait<0>();
        }
        __syncthreads();                 // S2: fills visible

        int buf = c & 1;
        uint32_t ah = sb + OFF_A + buf * 8192;
        uint32_t al = ah + 4096;
        uint32_t bh = sb + OFF_B + (buf * 2 + 0) * 16384 + bpanel;
        uint32_t bl = sb + OFF_B + (buf * 2 + 1) * 16384 + bpanel;

        #pragma unroll
        for (int kk = 0; kk < 2; ++kk) {
            uint32_t Ah[4], Al[4], Bh[2][4], Bl[2][4];
            ldsm4(Ah, ah + aoff[kk]);
            ldsm4(Al, al + aoff[kk]);
            ldsm4t(Bh[0], bh + boff0[kk]);
            ldsm4t(Bh[1], bh + boff1[kk]);
            // hh then lh on Bh (RAW distance 4)
            #pragma unroll
            for (int j = 0; j < 4; ++j)
                mma16816(acc[j], Ah, Bh[j >> 1][(j & 1) * 2], Bh[j >> 1][(j & 1) * 2 + 1]);
            #pragma unroll
            for (int j = 0; j < 4; ++j)
                mma16816(acc[j], Al, Bh[j >> 1][(j & 1) * 2], Bh[j >> 1][(j & 1) * 2 + 1]);
            ldsm4t(Bl[0], bl + boff0[kk]);
            ldsm4t(Bl[1], bl + boff1[kk]);
            #pragma unroll
            for (int j = 0; j < 4; ++j)
                mma16816(acc[j], Ah, Bl[j >> 1][(j & 1) * 2], Bl[j >> 1][(j & 1) * 2 + 1]);
        }
    }
    __syncthreads();   // mainloop done; A region free for reduction

    // ---- K-split reduction: odd (ksp=1) warps dump acc; even warps add ----
    float* Rs = (float*)(smem + OFF_RS);   // [8 pairs][32 lanes][16]
    const int pairIdx = wid >> 1;
    if (ksp == 1) {
        float* dst = Rs + (pairIdx * 32 + lane) * 16;
        #pragma unroll
        for (int j = 0; j < 4; ++j)
            *(float4*)(dst + j * 4) = make_float4(acc[j][0], acc[j][1], acc[j][2], acc[j][3]);
    }
    __syncthreads();
    if (ksp == 0) {
        const float* src = Rs + (pairIdx * 32 + lane) * 16;
        #pragma unroll
        for (int j = 0; j < 4; ++j) {
            float4 v = *(const float4*)(src + j * 4);
            acc[j][0] += v.x; acc[j][1] += v.y; acc[j][2] += v.z; acc[j][3] += v.w;
        }
    }
    __syncthreads();   // Rs reads done before Hs overwrites OFF_B region is separate; keep order

    // ---- epilogue: even warps -> bias + tanh -> Hs; stage W2 ----
    const int NO = half ? NL : NT;
    const float* W2 = half ? W2r : W2t;
    const float* b1 = half ? b1r : b1t;
    float* Hs  = (float*)(smem + OFF_HS);
    float* W2s = (float*)(smem + OFF_W2S);

    if (ksp == 0) {
        #pragma unroll
        for (int j = 0; j < 4; ++j) {
            int row = wm * 16 + (lane >> 2);
            int col = wn * 32 + j * 8 + (lane & 3) * 2;
            float bv0 = (col < H_)     ? __ldg(b1 + col)     : 0.f;
            float bv1 = (col + 1 < H_) ? __ldg(b1 + col + 1) : 0.f;
            Hs[row * HSS + col]           = tanhf(acc[j][0] + bv0);
            Hs[row * HSS + col + 1]       = tanhf(acc[j][1] + bv1);
            Hs[(row + 8) * HSS + col]     = tanhf(acc[j][2] + bv0);
            Hs[(row + 8) * HSS + col + 1] = tanhf(acc[j][3] + bv1);
        }
    }
    for (int i = tid; i < H_ * NO; i += THREADS) W2s[i] = __ldg(W2 + i);
    __syncthreads();

    // ---- tiny layer 2 + final tanh ----
    const float* b2 = half ? b2r : b2t;
    float* obase = half ? (out + B_TOT * NT) : out;

    for (int idx = tid; idx < BM * NO; idx += THREADS) {
        int row = idx / NO;
        int o   = idx - row * NO;
        const float* hrow = Hs + row * HSS;
        float s0 = 0.f, s1 = 0.f, s2 = 0.f, s3 = 0.f;
        #pragma unroll 4
        for (int k = 0; k < 124; k += 4) {
            s0 += hrow[k]     * W2s[k * NO + o];
            s1 += hrow[k + 1] * W2s[(k + 1) * NO + o];
            s2 += hrow[k + 2] * W2s[(k + 2) * NO + o];
            s3 += hrow[k + 3] * W2s[(k + 3) * NO + o];
        }
        float s = __ldg(b2 + o) + ((s0 + s1) + (s2 + s3))
                + hrow[124] * W2s[124 * NO + o];
        obase[(b0 + row) * NO + o] = tanhf(s);
    }
}

extern "C" void kernel_launch(void* const* d_in, const int* in_sizes, int n_in,
                              void* d_out, int out_size)
{
    const float* lstm_out     = (const float*)d_in[0];
    const int*   stack_index  = (const int*)  d_in[1];
    const int*   stack_len    = (const int*)  d_in[2];
    const int*   buffer_index = (const int*)  d_in[3];
    const int*   buffer_len   = (const int*)  d_in[4];
    const float* W1t          = (const float*)d_in[5];
    const float* b1t          = (const float*)d_in[6];
    const float* W2t          = (const float*)d_in[7];
    const float* b2t          = (const float*)d_in[8];
    const float* W1r          = (const float*)d_in[9];
    const float* b1r          = (const float*)d_in[10];
    const float* W2r          = (const float*)d_in[11];
    const float* b2r          = (const float*)d_in[12];
    float* out = (float*)d_out;

    prep_w_kernel<<<512, 256>>>(W1t, W1r);

    cudaFuncSetAttribute(parser_hmma_kernel,
                         cudaFuncAttributeMaxDynamicSharedMemorySize, SMEM_TOTAL);
    dim3 grid(B_TOT / BM, 2);
    parser_hmma_kernel<<<grid, THREADS, SMEM_TOTAL>>>(
        lstm_out, stack_index, stack_len, buffer_index, buffer_len,
        b1t, W2t, b2t, b1r, W2r, b2r, out);
}

// round 11
// speedup vs baseline: 1.5776x; 1.1551x over previous
#include <cuda_runtime.h>
#include <cuda_fp16.h>
#include <stdint.h>

// Problem constants
#define B_TOT   4096
#define T_      64
#define D_      250
#define K_      1000
#define H_      125
#define NT      4
#define NL      50

// Tiling
#define BM      32
#define BN      128
#define KCH     64
#define NCHUNK  16
#define THREADS 512
#define HSS     132

// smem layout (bytes)
#define OFF_A    0                    // [buf2][hi|lo 4096 each] -> 16384
#define OFF_B    16384                // [buf2][hi 16384] -> 32768
#define OFF_SOFF 49152                // 32*4 ints
#define OFF_RS   OFF_A                // k-split reduction buffer: 16384
#define OFF_HS   OFF_B                // epilogue: Hs[32][HSS] f32 = 16896
#define OFF_W2S  (OFF_B + 16896)      // W2 cache (<= 25000 B)
#define SMEM_TOTAL (OFF_W2S + 25088)

#define SW128(x) ((x) ^ ((((uint32_t)(x)) >> 3) & 0x70))

// Pre-split, pre-swizzled W1 fp16-hi images: [half][chunk][16384B]
__device__ __align__(16) uint8_t g_wbf[(size_t)2 * 16 * 16384];

__device__ __forceinline__ uint32_t smem_u32(const void* p) {
    uint32_t a;
    asm("{ .reg .u64 t; cvta.to.shared.u64 t, %1; cvt.u32.u64 %0, t; }"
        : "=r"(a) : "l"(p));
    return a;
}
__device__ __forceinline__ void ldsm4(uint32_t r[4], uint32_t a) {
    asm volatile("ldmatrix.sync.aligned.m8n8.x4.shared.b16 {%0,%1,%2,%3}, [%4];"
        : "=r"(r[0]), "=r"(r[1]), "=r"(r[2]), "=r"(r[3]) : "r"(a));
}
__device__ __forceinline__ void ldsm4t(uint32_t r[4], uint32_t a) {
    asm volatile("ldmatrix.sync.aligned.m8n8.x4.trans.shared.b16 {%0,%1,%2,%3}, [%4];"
        : "=r"(r[0]), "=r"(r[1]), "=r"(r[2]), "=r"(r[3]) : "r"(a));
}
__device__ __forceinline__ void mma16816(float c[4], const uint32_t a[4],
                                         uint32_t b0, uint32_t b1) {
    asm volatile(
        "mma.sync.aligned.m16n8k16.row.col.f32.f16.f16.f32 "
        "{%0,%1,%2,%3}, {%4,%5,%6,%7}, {%8,%9}, {%0,%1,%2,%3};"
        : "+f"(c[0]), "+f"(c[1]), "+f"(c[2]), "+f"(c[3])
        : "r"(a[0]), "r"(a[1]), "r"(a[2]), "r"(a[3]), "r"(b0), "r"(b1));
}
__device__ __forceinline__ void cp_async16(uint32_t s, const void* g) {
    asm volatile("cp.async.cg.shared.global [%0], [%1], 16;" :: "r"(s), "l"(g) : "memory");
}
__device__ __forceinline__ void cp_commit() {
    asm volatile("cp.async.commit_group;" ::: "memory");
}
template <int N> __device__ __forceinline__ void cp_wait() {
    asm volatile("cp.async.wait_group %0;" :: "n"(N) : "memory");
}
__device__ __forceinline__ uint32_t pack_h2(__half a, __half b) {
    __half2 h2 = __halves2half2(a, b);
    return *(uint32_t*)&h2;
}

// ------- prep W1: fp16 hi-only swizzled chunk images -------
__global__ void prep_w_kernel(const float* __restrict__ W1t,
                              const float* __restrict__ W1r)
{
    int idx  = blockIdx.x * blockDim.x + threadIdx.x;   // 0..131071
    int np   = idx & 63;
    int k    = (idx >> 6) & 1023;
    int half = idx >> 16;
    const float* W1 = half ? W1r : W1t;

    int n0 = np * 2;
    float w0 = 0.f, w1 = 0.f;
    if (k < K_) {
        if (n0 < H_)     w0 = W1[k * H_ + n0];
        if (n0 + 1 < H_) w1 = W1[k * H_ + n0 + 1];
    }
    __half h0 = __float2half_rn(w0);
    __half h1 = __float2half_rn(w1);

    int chunk = k >> 6, kloc = k & 63;
    int panel = n0 >> 6, nloc = n0 & 63;
    uint32_t sw = SW128((uint32_t)(kloc * 128 + nloc * 2));
    size_t o = ((size_t)half * 16 + chunk) * 16384 + panel * 8192 + sw;
    *(uint32_t*)(g_wbf + o) = pack_h2(h0, h1);
}

// -- main: 512 thr, warps = 2(M) x 4(N) x 2(Ksplit), fp16 2-pass split --
__global__ __launch_bounds__(THREADS, 2)
void parser_hmma_kernel(const float* __restrict__ lstm_out,
                        const int*   __restrict__ stack_index,
                        const int*   __restrict__ stack_len,
                        const int*   __restrict__ buffer_index,
                        const int*   __restrict__ buffer_len,
                        const float* __restrict__ b1t,
                        const float* __restrict__ W2t,
                        const float* __restrict__ b2t,
                        const float* __restrict__ b1r,
                        const float* __restrict__ W2r,
                        const float* __restrict__ b2r,
                        float* __restrict__ out)
{
    extern __shared__ char smem[];
    const uint32_t sb = smem_u32(smem);
    const int tid  = threadIdx.x;
    const int wid  = tid >> 5;
    const int lane = tid & 31;
    const int ksp  = wid & 1;
    const int wm   = (wid >> 1) & 1;
    const int wn   = wid >> 2;
    const int b0   = blockIdx.x * BM;
    const int half = blockIdx.y;

    int* soff = (int*)(smem + OFF_SOFF);
    if (tid < BM * 4) {
        int row = tid >> 2, s = tid & 3;
        int b = b0 + row;
        int t, valid;
        if (s < 3) { valid = (s < stack_len[b]);  t = stack_index[b * 3 + s]; }
        else       { valid = (0 < buffer_len[b]); t = buffer_index[b]; }
        soff[tid] = valid ? (b * T_ + t) * D_ : -1;
    }
    __syncthreads();

    // A-gather geometry: 2 items/thread
    const int kp0 = tid & 31,         m0 = tid >> 5;
    const int kp1 = (tid + 512) & 31, m1 = (tid + 512) >> 5;
    const uint32_t swst0 = SW128((uint32_t)(m0 * 128 + kp0 * 4));
    const uint32_t swst1 = SW128((uint32_t)(m1 * 128 + kp1 * 4));

    // ldmatrix geometry (chunk-invariant, 2 kk steps for this ksp)
    const int g = lane >> 3, r8 = lane & 7;
    const int arow = wm * 16 + (g & 1) * 8 + r8;
    const int acol = (g >> 1) * 8;
    const int brow = (g & 1) * 8 + r8;
    const int bc0  = ((wn * 32) & 63) + (g >> 1) * 8;
    const uint32_t bpanel = (uint32_t)(wn >> 1) * 8192;

    uint32_t aoff[2], boff0[2], boff1[2];
    #pragma unroll
    for (int kk = 0; kk < 2; ++kk) {
        int kb = (ksp * 2 + kk) * 16;
        aoff[kk]  = SW128((uint32_t)(arow * 128 + (kb + acol) * 2));
        boff0[kk] = SW128((uint32_t)((kb + brow) * 128 + bc0 * 2));
        boff1[kk] = SW128((uint32_t)((kb + brow) * 128 + (bc0 + 16) * 2));
    }

    float acc[4][4];
    #pragma unroll
    for (int j = 0; j < 4; ++j)
        #pragma unroll
        for (int e = 0; e < 4; ++e) acc[j][e] = 0.f;

    auto loadA = [&](int c, float2 (&rv)[2]) {
        #pragma unroll
        for (int it = 0; it < 2; ++it) {
            int kp = it ? kp1 : kp0;
            int m  = it ? m1  : m0;
            int k  = c * KCH + 2 * kp;
            float2 v = make_float2(0.f, 0.f);
            if (k < K_) {
                int slot = k / D_;
                int d    = k - slot * D_;
                int off  = soff[m * 4 + slot];
                if (off >= 0) v = *(const float2*)(lstm_out + off + d);
            }
            rv[it] = v;
        }
    };
    auto storeA = [&](int c, const float2 (&rv)[2]) {
        char* ah = smem + OFF_A + (c & 1) * 8192;
        char* al = ah + 4096;
        #pragma unroll
        for (int it = 0; it < 2; ++it) {
            float2 v = rv[it];
            __half hx = __float2half_rn(v.x);
            __half hy = __float2half_rn(v.y);
            __half lx = __float2half_rn(v.x - __half2float(hx));
            __half ly = __float2half_rn(v.y - __half2float(hy));
            uint32_t sw = it ? swst1 : swst0;
            *(uint32_t*)(ah + sw) = pack_h2(hx, hy);
            *(uint32_t*)(al + sw) = pack_h2(lx, ly);
        }
    };
    auto fillB = [&](int c) {
        int buf = c & 1;
        uint32_t dh = sb + OFF_B + buf * 16384;
        const uint8_t* sh = g_wbf + ((size_t)half * 16 + c) * 16384;
        #pragma unroll
        for (int it = 0; it < 2; ++it) {
            int o = (it * THREADS + tid) * 16;
            cp_async16(dh + o, sh + o);
        }
    };

    // prologue
    float2 rva[2], rvb[2];
    fillB(0); cp_commit();
    loadA(0, rva);
    loadA(1, rvb);

    #pragma unroll 2
    for (int c = 0; c < NCHUNK; ++c) {
        float2 (&rvc)[2] = (c & 1) ? rvb : rva;
        storeA(c, rvc);
        if (c + 2 < NCHUNK) loadA(c + 2, rvc);

        __syncthreads();                 // S1: B buffer (c+1)&1 free
        if (c + 1 < NCHUNK) {
            fillB(c + 1); cp_commit();
            cp_wait<1>();
        } else {
            cp_wait<0>();
        }
        __syncthreads();                 // S2: fills visible

        int buf = c & 1;
        uint32_t ah = sb + OFF_A + buf * 8192;
        uint32_t al = ah + 4096;
        uint32_t bh = sb + OFF_B + buf * 16384 + bpanel;

        #pragma unroll
        for (int kk = 0; kk < 2; ++kk) {
            uint32_t Ah[4], Al[4], Bh[2][4];
            ldsm4(Ah, ah + aoff[kk]);
            ldsm4(Al, al + aoff[kk]);
            ldsm4t(Bh[0], bh + boff0[kk]);
            ldsm4t(Bh[1], bh + boff1[kk]);
            // 2-pass: hh then lh (computes A_full * B_hi exactly)
            #pragma unroll
            for (int j = 0; j < 4; ++j)
                mma16816(acc[j], Ah, Bh[j >> 1][(j & 1) * 2], Bh[j >> 1][(j & 1) * 2 + 1]);
            #pragma unroll
            for (int j = 0; j < 4; ++j)
                mma16816(acc[j], Al, Bh[j >> 1][(j & 1) * 2], Bh[j >> 1][(j & 1) * 2 + 1]);
        }
    }
    __syncthreads();   // mainloop done; A region free for reduction

    // ---- K-split reduction ----
    float* Rs = (float*)(smem + OFF_RS);
    const int pairIdx = wid >> 1;
    if (ksp == 1) {
        float* dst = Rs + (pairIdx * 32 + lane) * 16;
        #pragma unroll
        for (int j = 0; j < 4; ++j)
            *(float4*)(dst + j * 4) = make_float4(acc[j][0], acc[j][1], acc[j][2], acc[j][3]);
    }
    __syncthreads();
    if (ksp == 0) {
        const float* src = Rs + (pairIdx * 32 + lane) * 16;
        #pragma unroll
        for (int j = 0; j < 4; ++j) {
            float4 v = *(const float4*)(src + j * 4);
            acc[j][0] += v.x; acc[j][1] += v.y; acc[j][2] += v.z; acc[j][3] += v.w;
        }
    }
    __syncthreads();

    // ---- epilogue: even warps -> bias + tanh -> Hs; stage W2 ----
    const int NO = half ? NL : NT;
    const float* W2 = half ? W2r : W2t;
    const float* b1 = half ? b1r : b1t;
    float* Hs  = (float*)(smem + OFF_HS);
    float* W2s = (float*)(smem + OFF_W2S);

    if (ksp == 0) {
        #pragma unroll
        for (int j = 0; j < 4; ++j) {
            int row = wm * 16 + (lane >> 2);
            int col = wn * 32 + j * 8 + (lane & 3) * 2;
            float bv0 = (col < H_)     ? __ldg(b1 + col)     : 0.f;
            float bv1 = (col + 1 < H_) ? __ldg(b1 + col + 1) : 0.f;
            Hs[row * HSS + col]           = tanhf(acc[j][0] + bv0);
            Hs[row * HSS + col + 1]       = tanhf(acc[j][1] + bv1);
            Hs[(row + 8) * HSS + col]     = tanhf(acc[j][2] + bv0);
            Hs[(row + 8) * HSS + col + 1] = tanhf(acc[j][3] + bv1);
        }
    }
    for (int i = tid; i < H_ * NO; i += THREADS) W2s[i] = __ldg(W2 + i);
    __syncthreads();

    // ---- tiny layer 2 + final tanh ----
    const float* b2 = half ? b2r : b2t;
    float* obase = half ? (out + B_TOT * NT) : out;

    for (int idx = tid; idx < BM * NO; idx += THREADS) {
        int row = idx / NO;
        int o   = idx - row * NO;
        const float* hrow = Hs + row * HSS;
        float s0 = 0.f, s1 = 0.f, s2 = 0.f, s3 = 0.f;
        #pragma unroll 4
        for (int k = 0; k < 124; k += 4) {
            s0 += hrow[k]     * W2s[k * NO + o];
            s1 += hrow[k + 1] * W2s[(k + 1) * NO + o];
            s2 += hrow[k + 2] * W2s[(k + 2) * NO + o];
            s3 += hrow[k + 3] * W2s[(k + 3) * NO + o];
        }
        float s = __ldg(b2 + o) + ((s0 + s1) + (s2 + s3))
                + hrow[124] * W2s[124 * NO + o];
        obase[(b0 + row) * NO + o] = tanhf(s);
    }
}

extern "C" void kernel_launch(void* const* d_in, const int* in_sizes, int n_in,
                              void* d_out, int out_size)
{
    const float* lstm_out     = (const float*)d_in[0];
    const int*   stack_index  = (const int*)  d_in[1];
    const int*   stack_len    = (const int*)  d_in[2];
    const int*   buffer_index = (const int*)  d_in[3];
    const int*   buffer_len   = (const int*)  d_in[4];
    const float* W1t          = (const float*)d_in[5];
    const float* b1t          = (const float*)d_in[6];
    const float* W2t          = (const float*)d_in[7];
    const float* b2t          = (const float*)d_in[8];
    const float* W1r          = (const float*)d_in[9];
    const float* b1r          = (const float*)d_in[10];
    const float* W2r          = (const float*)d_in[11];
    const float* b2r          = (const float*)d_in[12];
    float* out = (float*)d_out;

    prep_w_kernel<<<512, 256>>>(W1t, W1r);

    cudaFuncSetAttribute(parser_hmma_kernel,
                         cudaFuncAttributeMaxDynamicSharedMemorySize, SMEM_TOTAL);
    dim3 grid(B_TOT / BM, 2);
    parser_hmma_kernel<<<grid, THREADS, SMEM_TOTAL>>>(
        lstm_out, stack_index, stack_len, buffer_index, buffer_len,
        b1t, W2t, b2t, b1r, W2r, b2r, out);
}

// round 12
// speedup vs baseline: 1.6565x; 1.0500x over previous
#include <cuda_runtime.h>
#include <cuda_fp16.h>
#include <stdint.h>

// Problem constants
#define B_TOT   4096
#define T_      64
#define D_      250
#define K_      1000
#define H_      125
#define NT      4
#define NL      50

// Tiling
#define BM      32
#define BN      128
#define KCH     128
#define NCHUNK  8
#define THREADS 512
#define HSS     132

// smem layout (bytes)
#define OFF_A    0                    // [buf2][hi 8192 | lo 8192] -> 32768
#define OFF_B    32768                // [buf2][32768] -> 65536
#define OFF_SOFF 98304                // 32*4 ints
#define SMEM_TOTAL (98304 + 512)
#define OFF_RS   OFF_A                // k-split reduction buffer (16384)
#define OFF_HS   OFF_B                // epilogue: Hs[32][HSS] f32 = 16896
#define OFF_W2S  (OFF_B + 16896)      // W2 cache (<= 25000 B)

#define SW128(x) ((x) ^ ((((uint32_t)(x)) >> 3) & 0x70))

// Pre-split, pre-swizzled W1 fp16 images: [half][chunk8][kpanel2][npanel2][8192]
__device__ __align__(16) uint8_t g_wbf[(size_t)2 * 8 * 32768];

__device__ __forceinline__ uint32_t smem_u32(const void* p) {
    uint32_t a;
    asm("{ .reg .u64 t; cvta.to.shared.u64 t, %1; cvt.u32.u64 %0, t; }"
        : "=r"(a) : "l"(p));
    return a;
}
__device__ __forceinline__ void ldsm4(uint32_t r[4], uint32_t a) {
    asm volatile("ldmatrix.sync.aligned.m8n8.x4.shared.b16 {%0,%1,%2,%3}, [%4];"
        : "=r"(r[0]), "=r"(r[1]), "=r"(r[2]), "=r"(r[3]) : "r"(a));
}
__device__ __forceinline__ void ldsm4t(uint32_t r[4], uint32_t a) {
    asm volatile("ldmatrix.sync.aligned.m8n8.x4.trans.shared.b16 {%0,%1,%2,%3}, [%4];"
        : "=r"(r[0]), "=r"(r[1]), "=r"(r[2]), "=r"(r[3]) : "r"(a));
}
__device__ __forceinline__ void mma16816(float c[4], const uint32_t a[4],
                                         uint32_t b0, uint32_t b1) {
    asm volatile(
        "mma.sync.aligned.m16n8k16.row.col.f32.f16.f16.f32 "
        "{%0,%1,%2,%3}, {%4,%5,%6,%7}, {%8,%9}, {%0,%1,%2,%3};"
        : "+f"(c[0]), "+f"(c[1]), "+f"(c[2]), "+f"(c[3])
        : "r"(a[0]), "r"(a[1]), "r"(a[2]), "r"(a[3]), "r"(b0), "r"(b1));
}
__device__ __forceinline__ void cp_async16(uint32_t s, const void* g) {
    asm volatile("cp.async.cg.shared.global [%0], [%1], 16;" :: "r"(s), "l"(g) : "memory");
}
__device__ __forceinline__ void cp_commit() {
    asm volatile("cp.async.commit_group;" ::: "memory");
}
template <int N> __device__ __forceinline__ void cp_wait() {
    asm volatile("cp.async.wait_group %0;" :: "n"(N) : "memory");
}
__device__ __forceinline__ uint32_t pack_h2(__half a, __half b) {
    __half2 h2 = __halves2half2(a, b);
    return *(uint32_t*)&h2;
}

// ------- prep W1: fp16 hi-only swizzled chunk images -------
__global__ void prep_w_kernel(const float* __restrict__ W1t,
                              const float* __restrict__ W1r)
{
    int idx  = blockIdx.x * blockDim.x + threadIdx.x;   // 0..131071
    int np   = idx & 63;
    int k    = (idx >> 6) & 1023;
    int half = idx >> 16;
    const float* W1 = half ? W1r : W1t;

    int n0 = np * 2;
    float w0 = 0.f, w1 = 0.f;
    if (k < K_) {
        if (n0 < H_)     w0 = W1[k * H_ + n0];
        if (n0 + 1 < H_) w1 = W1[k * H_ + n0 + 1];
    }
    __half h0 = __float2half_rn(w0);
    __half h1 = __float2half_rn(w1);

    int chunk  = k >> 7;
    int kpanel = (k >> 6) & 1;
    int kloc   = k & 63;
    int npanel = n0 >> 6, nloc = n0 & 63;
    uint32_t sw = SW128((uint32_t)(kloc * 128 + nloc * 2));
    size_t o = ((size_t)half * 8 + chunk) * 32768
             + (size_t)kpanel * 16384 + (size_t)npanel * 8192 + sw;
    *(uint32_t*)(g_wbf + o) = pack_h2(h0, h1);
}

// -- main: 512 thr, warps = 2(M) x 4(N) x 2(Ksplit), fp16 2-pass, KCH=128 --
__global__ __launch_bounds__(THREADS, 2)
void parser_hmma_kernel(const float* __restrict__ lstm_out,
                        const int*   __restrict__ stack_index,
                        const int*   __restrict__ stack_len,
                        const int*   __restrict__ buffer_index,
                        const int*   __restrict__ buffer_len,
                        const float* __restrict__ b1t,
                        const float* __restrict__ W2t,
                        const float* __restrict__ b2t,
                        const float* __restrict__ b1r,
                        const float* __restrict__ W2r,
                        const float* __restrict__ b2r,
                        float* __restrict__ out)
{
    extern __shared__ char smem[];
    const uint32_t sb = smem_u32(smem);
    const int tid  = threadIdx.x;
    const int wid  = tid >> 5;
    const int lane = tid & 31;
    const int ksp  = wid & 1;          // K-split: sub-panel ksp
    const int wm   = (wid >> 1) & 1;
    const int wn   = wid >> 2;
    const int b0   = blockIdx.x * BM;
    const int half = blockIdx.y;

    int* soff = (int*)(smem + OFF_SOFF);
    if (tid < BM * 4) {
        int row = tid >> 2, s = tid & 3;
        int b = b0 + row;
        int t, valid;
        if (s < 3) { valid = (s < stack_len[b]);  t = stack_index[b * 3 + s]; }
        else       { valid = (0 < buffer_len[b]); t = buffer_index[b]; }
        soff[tid] = valid ? (b * T_ + t) * D_ : -1;
    }
    __syncthreads();

    // A-gather geometry: 4 items/thread, kp constant across items
    const int kp     = tid & 63;       // k-pair within chunk (0..63)
    const int mbase  = tid >> 6;       // m = it*8 + mbase
    const uint32_t swstbase = (uint32_t)(kp >> 5) * 4096
                            + SW128((uint32_t)(mbase * 128 + (kp & 31) * 4));

    // ldmatrix geometry (chunk-invariant; ksp handled via base pointers)
    const int g = lane >> 3, r8 = lane & 7;
    const int arow = wm * 16 + (g & 1) * 8 + r8;
    const int acol = (g >> 1) * 8;
    const int brow = (g & 1) * 8 + r8;
    const int bc0  = ((wn * 32) & 63) + (g >> 1) * 8;
    const uint32_t bnp = (uint32_t)(wn >> 1) * 8192;

    uint32_t aoff[4], boff0[4], boff1[4];
    #pragma unroll
    for (int kk = 0; kk < 4; ++kk) {
        int kb = kk * 16;
        aoff[kk]  = SW128((uint32_t)(arow * 128 + (kb + acol) * 2));
        boff0[kk] = SW128((uint32_t)((kb + brow) * 128 + bc0 * 2));
        boff1[kk] = SW128((uint32_t)((kb + brow) * 128 + (bc0 + 16) * 2));
    }

    float acc[4][4];
    #pragma unroll
    for (int j = 0; j < 4; ++j)
        #pragma unroll
        for (int e = 0; e < 4; ++e) acc[j][e] = 0.f;

    auto loadA = [&](int c, float2 (&rv)[4]) {
        int k = c * KCH + 2 * kp;
        #pragma unroll
        for (int it = 0; it < 4; ++it) rv[it] = make_float2(0.f, 0.f);
        if (k < K_) {
            int slot = k / D_;
            int d    = k - slot * D_;
            #pragma unroll
            for (int it = 0; it < 4; ++it) {
                int m   = it * 8 + mbase;
                int off = soff[m * 4 + slot];
                if (off >= 0) rv[it] = *(const float2*)(lstm_out + off + d);
            }
        }
    };
    auto storeA = [&](int c, const float2 (&rv)[4]) {
        char* ah = smem + OFF_A + (c & 1) * 16384;
        char* al = ah + 8192;
        #pragma unroll
        for (int it = 0; it < 4; ++it) {
            float2 v = rv[it];
            __half hx = __float2half_rn(v.x);
            __half hy = __float2half_rn(v.y);
            __half lx = __float2half_rn(v.x - __half2float(hx));
            __half ly = __float2half_rn(v.y - __half2float(hy));
            uint32_t sw = swstbase + it * 1024;
            *(uint32_t*)(ah + sw) = pack_h2(hx, hy);
            *(uint32_t*)(al + sw) = pack_h2(lx, ly);
        }
    };
    auto fillB = [&](int c) {
        uint32_t dh = sb + OFF_B + (c & 1) * 32768;
        const uint8_t* sh = g_wbf + ((size_t)half * 8 + c) * 32768;
        #pragma unroll
        for (int it = 0; it < 4; ++it) {
            int o = (it * THREADS + tid) * 16;
            cp_async16(dh + o, sh + o);
        }
    };

    // prologue
    float2 rv[4];
    fillB(0); cp_commit();
    loadA(0, rv);

    #pragma unroll 2
    for (int c = 0; c < NCHUNK; ++c) {
        storeA(c, rv);                    // A(c) -> smem (buffer parity c&1 is free)
        if (c + 1 < NCHUNK) loadA(c + 1, rv);   // LDG covered by chunk-c compute

        __syncthreads();                  // S1: B buffer (c+1)&1 free
        if (c + 1 < NCHUNK) {
            fillB(c + 1); cp_commit();
            cp_wait<1>();                 // B(c) arrived
        } else {
            cp_wait<0>();
        }
        __syncthreads();                  // S2: A stores + B fills visible

        int buf = c & 1;
        uint32_t ah = sb + OFF_A + buf * 16384 + ksp * 4096;
        uint32_t al = ah + 8192;
        uint32_t bh = sb + OFF_B + buf * 32768 + ksp * 16384 + bnp;

        #pragma unroll
        for (int kk = 0; kk < 4; ++kk) {
            uint32_t Ah[4], Al[4], Bh[2][4];
            ldsm4(Ah, ah + aoff[kk]);
            ldsm4(Al, al + aoff[kk]);
            ldsm4t(Bh[0], bh + boff0[kk]);
            ldsm4t(Bh[1], bh + boff1[kk]);
            // 2-pass: hh then lh (A_full * B_hi exactly)
            #pragma unroll
            for (int j = 0; j < 4; ++j)
                mma16816(acc[j], Ah, Bh[j >> 1][(j & 1) * 2], Bh[j >> 1][(j & 1) * 2 + 1]);
            #pragma unroll
            for (int j = 0; j < 4; ++j)
                mma16816(acc[j], Al, Bh[j >> 1][(j & 1) * 2], Bh[j >> 1][(j & 1) * 2 + 1]);
        }
    }
    __syncthreads();   // mainloop done; A region free for reduction

    // ---- K-split reduction ----
    float* Rs = (float*)(smem + OFF_RS);
    const int pairIdx = wid >> 1;
    if (ksp == 1) {
        float* dst = Rs + (pairIdx * 32 + lane) * 16;
        #pragma unroll
        for (int j = 0; j < 4; ++j)
            *(float4*)(dst + j * 4) = make_float4(acc[j][0], acc[j][1], acc[j][2], acc[j][3]);
    }
    __syncthreads();
    if (ksp == 0) {
        const float* src = Rs + (pairIdx * 32 + lane) * 16;
        #pragma unroll
        for (int j = 0; j < 4; ++j) {
            float4 v = *(const float4*)(src + j * 4);
            acc[j][0] += v.x; acc[j][1] += v.y; acc[j][2] += v.z; acc[j][3] += v.w;
        }
    }
    __syncthreads();

    // ---- epilogue: even warps -> bias + tanh -> Hs; stage W2 ----
    const int NO = half ? NL : NT;
    const float* W2 = half ? W2r : W2t;
    const float* b1 = half ? b1r : b1t;
    float* Hs  = (float*)(smem + OFF_HS);
    float* W2s = (float*)(smem + OFF_W2S);

    if (ksp == 0) {
        #pragma unroll
        for (int j = 0; j < 4; ++j) {
            int row = wm * 16 + (lane >> 2);
            int col = wn * 32 + j * 8 + (lane & 3) * 2;
            float bv0 = (col < H_)     ? __ldg(b1 + col)     : 0.f;
            float bv1 = (col + 1 < H_) ? __ldg(b1 + col + 1) : 0.f;
            Hs[row * HSS + col]           = tanhf(acc[j][0] + bv0);
            Hs[row * HSS + col + 1]       = tanhf(acc[j][1] + bv1);
            Hs[(row + 8) * HSS + col]     = tanhf(acc[j][2] + bv0);
            Hs[(row + 8) * HSS + col + 1] = tanhf(acc[j][3] + bv1);
        }
    }
    for (int i = tid; i < H_ * NO; i += THREADS) W2s[i] = __ldg(W2 + i);
    __syncthreads();

    // ---- tiny layer 2 + final tanh ----
    const float* b2 = half ? b2r : b2t;
    float* obase = half ? (out + B_TOT * NT) : out;

    for (int idx = tid; idx < BM * NO; idx += THREADS) {
        int row = idx / NO;
        int o   = idx - row * NO;
        const float* hrow = Hs + row * HSS;
        float s0 = 0.f, s1 = 0.f, s2 = 0.f, s3 = 0.f;
        #pragma unroll 4
        for (int k = 0; k < 124; k += 4) {
            s0 += hrow[k]     * W2s[k * NO + o];
            s1 += hrow[k + 1] * W2s[(k + 1) * NO + o];
            s2 += hrow[k + 2] * W2s[(k + 2) * NO + o];
            s3 += hrow[k + 3] * W2s[(k + 3) * NO + o];
        }
        float s = __ldg(b2 + o) + ((s0 + s1) + (s2 + s3))
                + hrow[124] * W2s[124 * NO + o];
        obase[(b0 + row) * NO + o] = tanhf(s);
    }
}

extern "C" void kernel_launch(void* const* d_in, const int* in_sizes, int n_in,
                              void* d_out, int out_size)
{
    const float* lstm_out     = (const float*)d_in[0];
    const int*   stack_index  = (const int*)  d_in[1];
    const int*   stack_len    = (const int*)  d_in[2];
    const int*   buffer_index = (const int*)  d_in[3];
    const int*   buffer_len   = (const int*)  d_in[4];
    const float* W1t          = (const float*)d_in[5];
    const float* b1t          = (const float*)d_in[6];
    const float* W2t          = (const float*)d_in[7];
    const float* b2t          = (const float*)d_in[8];
    const float* W1r          = (const float*)d_in[9];
    const float* b1r          = (const float*)d_in[10];
    const float* W2r          = (const float*)d_in[11];
    const float* b2r          = (const float*)d_in[12];
    float* out = (float*)d_out;

    prep_w_kernel<<<512, 256>>>(W1t, W1r);

    cudaFuncSetAttribute(parser_hmma_kernel,
                         cudaFuncAttributeMaxDynamicSharedMemorySize, SMEM_TOTAL);
    dim3 grid(B_TOT / BM, 2);
    parser_hmma_kernel<<<grid, THREADS, SMEM_TOTAL>>>(
        lstm_out, stack_index, stack_len, buffer_index, buffer_len,
        b1t, W2t, b2t, b1r, W2r, b2r, out);
}

// round 13
// speedup vs baseline: 1.8471x; 1.1151x over previous
#include <cuda_runtime.h>
#include <cuda_fp16.h>
#include <stdint.h>

// Problem constants
#define B_TOT   4096
#define T_      64
#define D_      250
#define K_      1000
#define H_      125
#define NT      4
#define NL      50

// Tiling
#define BM      32
#define BN      128
#define KCH     128
#define NCHUNK  8
#define THREADS 512
#define HSS     132

// smem layout (bytes)
#define OFF_A    0                    // [buf2][8192]  (fp16 hi only) -> 16384
#define OFF_B    16384                // [buf2][32768] -> 65536
#define OFF_SOFF 81920                // 32*4 ints
#define SMEM_TOTAL (81920 + 512)
#define OFF_RS   OFF_A                // k-split reduction buffer (16384)
#define OFF_HS   OFF_B                // epilogue: Hs[32][HSS] f32 = 16896
#define OFF_W2S  (OFF_B + 16896)      // W2 cache (<= 25000 B)

#define SW128(x) ((x) ^ ((((uint32_t)(x)) >> 3) & 0x70))

// Pre-swizzled W1 fp16 images: [half][chunk8][kpanel2][npanel2][8192]
__device__ __align__(16) uint8_t g_wbf[(size_t)2 * 8 * 32768];

__device__ __forceinline__ uint32_t smem_u32(const void* p) {
    uint32_t a;
    asm("{ .reg .u64 t; cvta.to.shared.u64 t, %1; cvt.u32.u64 %0, t; }"
        : "=r"(a) : "l"(p));
    return a;
}
__device__ __forceinline__ void ldsm4(uint32_t r[4], uint32_t a) {
    asm volatile("ldmatrix.sync.aligned.m8n8.x4.shared.b16 {%0,%1,%2,%3}, [%4];"
        : "=r"(r[0]), "=r"(r[1]), "=r"(r[2]), "=r"(r[3]) : "r"(a));
}
__device__ __forceinline__ void ldsm4t(uint32_t r[4], uint32_t a) {
    asm volatile("ldmatrix.sync.aligned.m8n8.x4.trans.shared.b16 {%0,%1,%2,%3}, [%4];"
        : "=r"(r[0]), "=r"(r[1]), "=r"(r[2]), "=r"(r[3]) : "r"(a));
}
__device__ __forceinline__ void mma16816(float c[4], const uint32_t a[4],
                                         uint32_t b0, uint32_t b1) {
    asm volatile(
        "mma.sync.aligned.m16n8k16.row.col.f32.f16.f16.f32 "
        "{%0,%1,%2,%3}, {%4,%5,%6,%7}, {%8,%9}, {%0,%1,%2,%3};"
        : "+f"(c[0]), "+f"(c[1]), "+f"(c[2]), "+f"(c[3])
        : "r"(a[0]), "r"(a[1]), "r"(a[2]), "r"(a[3]), "r"(b0), "r"(b1));
}
__device__ __forceinline__ void cp_async16(uint32_t s, const void* g) {
    asm volatile("cp.async.cg.shared.global [%0], [%1], 16;" :: "r"(s), "l"(g) : "memory");
}
__device__ __forceinline__ void cp_commit() {
    asm volatile("cp.async.commit_group;" ::: "memory");
}
template <int N> __device__ __forceinline__ void cp_wait() {
    asm volatile("cp.async.wait_group %0;" :: "n"(N) : "memory");
}
__device__ __forceinline__ uint32_t pack_h2(__half a, __half b) {
    __half2 h2 = __halves2half2(a, b);
    return *(uint32_t*)&h2;
}

// ------- prep W1: fp16 swizzled chunk images -------
__global__ void prep_w_kernel(const float* __restrict__ W1t,
                              const float* __restrict__ W1r)
{
    int idx  = blockIdx.x * blockDim.x + threadIdx.x;   // 0..131071
    int np   = idx & 63;
    int k    = (idx >> 6) & 1023;
    int half = idx >> 16;
    const float* W1 = half ? W1r : W1t;

    int n0 = np * 2;
    float w0 = 0.f, w1 = 0.f;
    if (k < K_) {
        if (n0 < H_)     w0 = W1[k * H_ + n0];
        if (n0 + 1 < H_) w1 = W1[k * H_ + n0 + 1];
    }
    __half h0 = __float2half_rn(w0);
    __half h1 = __float2half_rn(w1);

    int chunk  = k >> 7;
    int kpanel = (k >> 6) & 1;
    int kloc   = k & 63;
    int npanel = n0 >> 6, nloc = n0 & 63;
    uint32_t sw = SW128((uint32_t)(kloc * 128 + nloc * 2));
    size_t o = ((size_t)half * 8 + chunk) * 32768
             + (size_t)kpanel * 16384 + (size_t)npanel * 8192 + sw;
    *(uint32_t*)(g_wbf + o) = pack_h2(h0, h1);
}

// -- main: 512 thr, warps = 2(M) x 4(N) x 2(Ksplit), fp16 single-pass, KCH=128 --
__global__ __launch_bounds__(THREADS, 2)
void parser_hmma_kernel(const float* __restrict__ lstm_out,
                        const int*   __restrict__ stack_index,
                        const int*   __restrict__ stack_len,
                        const int*   __restrict__ buffer_index,
                        const int*   __restrict__ buffer_len,
                        const float* __restrict__ b1t,
                        const float* __restrict__ W2t,
                        const float* __restrict__ b2t,
                        const float* __restrict__ b1r,
                        const float* __restrict__ W2r,
                        const float* __restrict__ b2r,
                        float* __restrict__ out)
{
    extern __shared__ char smem[];
    const uint32_t sb = smem_u32(smem);
    const int tid  = threadIdx.x;
    const int wid  = tid >> 5;
    const int lane = tid & 31;
    const int ksp  = wid & 1;
    const int wm   = (wid >> 1) & 1;
    const int wn   = wid >> 2;
    const int b0   = blockIdx.x * BM;
    const int half = blockIdx.y;

    int* soff = (int*)(smem + OFF_SOFF);
    if (tid < BM * 4) {
        int row = tid >> 2, s = tid & 3;
        int b = b0 + row;
        int t, valid;
        if (s < 3) { valid = (s < stack_len[b]);  t = stack_index[b * 3 + s]; }
        else       { valid = (0 < buffer_len[b]); t = buffer_index[b]; }
        soff[tid] = valid ? (b * T_ + t) * D_ : -1;
    }
    __syncthreads();

    // A-gather geometry: 4 items/thread, kp constant across items
    const int kp     = tid & 63;
    const int mbase  = tid >> 6;
    const uint32_t swstbase = (uint32_t)(kp >> 5) * 4096
                            + SW128((uint32_t)(mbase * 128 + (kp & 31) * 4));

    // ldmatrix geometry
    const int g = lane >> 3, r8 = lane & 7;
    const int arow = wm * 16 + (g & 1) * 8 + r8;
    const int acol = (g >> 1) * 8;
    const int brow = (g & 1) * 8 + r8;
    const int bc0  = ((wn * 32) & 63) + (g >> 1) * 8;
    const uint32_t bnp = (uint32_t)(wn >> 1) * 8192;

    uint32_t aoff[4], boff0[4], boff1[4];
    #pragma unroll
    for (int kk = 0; kk < 4; ++kk) {
        int kb = kk * 16;
        aoff[kk]  = SW128((uint32_t)(arow * 128 + (kb + acol) * 2));
        boff0[kk] = SW128((uint32_t)((kb + brow) * 128 + bc0 * 2));
        boff1[kk] = SW128((uint32_t)((kb + brow) * 128 + (bc0 + 16) * 2));
    }

    float acc[4][4];
    #pragma unroll
    for (int j = 0; j < 4; ++j)
        #pragma unroll
        for (int e = 0; e < 4; ++e) acc[j][e] = 0.f;

    auto loadA = [&](int c, float2 (&rv)[4]) {
        int k = c * KCH + 2 * kp;
        #pragma unroll
        for (int it = 0; it < 4; ++it) rv[it] = make_float2(0.f, 0.f);
        if (k < K_) {
            int slot = k / D_;
            int d    = k - slot * D_;
            #pragma unroll
            for (int it = 0; it < 4; ++it) {
                int m   = it * 8 + mbase;
                int off = soff[m * 4 + slot];
                if (off >= 0) rv[it] = *(const float2*)(lstm_out + off + d);
            }
        }
    };
    auto storeA = [&](int c, const float2 (&rv)[4]) {
        char* ah = smem + OFF_A + (c & 1) * 8192;
        #pragma unroll
        for (int it = 0; it < 4; ++it) {
            float2 v = rv[it];
            __half hx = __float2half_rn(v.x);
            __half hy = __float2half_rn(v.y);
            *(uint32_t*)(ah + swstbase + it * 1024) = pack_h2(hx, hy);
        }
    };
    auto fillB = [&](int c) {
        uint32_t dh = sb + OFF_B + (c & 1) * 32768;
        const uint8_t* sh = g_wbf + ((size_t)half * 8 + c) * 32768;
        #pragma unroll
        for (int it = 0; it < 4; ++it) {
            int o = (it * THREADS + tid) * 16;
            cp_async16(dh + o, sh + o);
        }
    };

    // prologue
    float2 rv[4];
    fillB(0); cp_commit();
    loadA(0, rv);

    #pragma unroll 2
    for (int c = 0; c < NCHUNK; ++c) {
        storeA(c, rv);
        if (c + 1 < NCHUNK) loadA(c + 1, rv);

        __syncthreads();                  // S1: B buffer (c+1)&1 free
        if (c + 1 < NCHUNK) {
            fillB(c + 1); cp_commit();
            cp_wait<1>();                 // B(c) arrived
        } else {
            cp_wait<0>();
        }
        __syncthreads();                  // S2: A stores + B fills visible

        int buf = c & 1;
        uint32_t ah = sb + OFF_A + buf * 8192 + ksp * 4096;
        uint32_t bh = sb + OFF_B + buf * 32768 + ksp * 16384 + bnp;

        #pragma unroll
        for (int kk = 0; kk < 4; ++kk) {
            uint32_t Ah[4], Bh[2][4];
            ldsm4(Ah, ah + aoff[kk]);
            ldsm4t(Bh[0], bh + boff0[kk]);
            ldsm4t(Bh[1], bh + boff1[kk]);
            #pragma unroll
            for (int j = 0; j < 4; ++j)
                mma16816(acc[j], Ah, Bh[j >> 1][(j & 1) * 2], Bh[j >> 1][(j & 1) * 2 + 1]);
        }
    }
    __syncthreads();   // mainloop done; A region free for reduction

    // ---- K-split reduction ----
    float* Rs = (float*)(smem + OFF_RS);
    const int pairIdx = wid >> 1;
    if (ksp == 1) {
        float* dst = Rs + (pairIdx * 32 + lane) * 16;
        #pragma unroll
        for (int j = 0; j < 4; ++j)
            *(float4*)(dst + j * 4) = make_float4(acc[j][0], acc[j][1], acc[j][2], acc[j][3]);
    }
    __syncthreads();
    if (ksp == 0) {
        const float* src = Rs + (pairIdx * 32 + lane) * 16;
        #pragma unroll
        for (int j = 0; j < 4; ++j) {
            float4 v = *(const float4*)(src + j * 4);
            acc[j][0] += v.x; acc[j][1] += v.y; acc[j][2] += v.z; acc[j][3] += v.w;
        }
    }
    __syncthreads();

    // ---- epilogue: even warps -> bias + tanh -> Hs; stage W2 ----
    const int NO = half ? NL : NT;
    const float* W2 = half ? W2r : W2t;
    const float* b1 = half ? b1r : b1t;
    float* Hs  = (float*)(smem + OFF_HS);
    float* W2s = (float*)(smem + OFF_W2S);

    if (ksp == 0) {
        #pragma unroll
        for (int j = 0; j < 4; ++j) {
            int row = wm * 16 + (lane >> 2);
            int col = wn * 32 + j * 8 + (lane & 3) * 2;
            float bv0 = (col < H_)     ? __ldg(b1 + col)     : 0.f;
            float bv1 = (col + 1 < H_) ? __ldg(b1 + col + 1) : 0.f;
            Hs[row * HSS + col]           = tanhf(acc[j][0] + bv0);
            Hs[row * HSS + col + 1]       = tanhf(acc[j][1] + bv1);
            Hs[(row + 8) * HSS + col]     = tanhf(acc[j][2] + bv0);
            Hs[(row + 8) * HSS + col + 1] = tanhf(acc[j][3] + bv1);
        }
    }
    for (int i = tid; i < H_ * NO; i += THREADS) W2s[i] = __ldg(W2 + i);
    __syncthreads();

    // ---- tiny layer 2 + final tanh ----
    const float* b2 = half ? b2r : b2t;
    float* obase = half ? (out + B_TOT * NT) : out;

    for (int idx = tid; idx < BM * NO; idx += THREADS) {
        int row = idx / NO;
        int o   = idx - row * NO;
        const float* hrow = Hs + row * HSS;
        float s0 = 0.f, s1 = 0.f, s2 = 0.f, s3 = 0.f;
        #pragma unroll 4
        for (int k = 0; k < 124; k += 4) {
            s0 += hrow[k]     * W2s[k * NO + o];
            s1 += hrow[k + 1] * W2s[(k + 1) * NO + o];
            s2 += hrow[k + 2] * W2s[(k + 2) * NO + o];
            s3 += hrow[k + 3] * W2s[(k + 3) * NO + o];
        }
        float s = __ldg(b2 + o) + ((s0 + s1) + (s2 + s3))
                + hrow[124] * W2s[124 * NO + o];
        obase[(b0 + row) * NO + o] = tanhf(s);
    }
}

extern "C" void kernel_launch(void* const* d_in, const int* in_sizes, int n_in,
                              void* d_out, int out_size)
{
    const float* lstm_out     = (const float*)d_in[0];
    const int*   stack_index  = (const int*)  d_in[1];
    const int*   stack_len    = (const int*)  d_in[2];
    const int*   buffer_index = (const int*)  d_in[3];
    const int*   buffer_len   = (const int*)  d_in[4];
    const float* W1t          = (const float*)d_in[5];
    const float* b1t          = (const float*)d_in[6];
    const float* W2t          = (const float*)d_in[7];
    const float* b2t          = (const float*)d_in[8];
    const float* W1r          = (const float*)d_in[9];
    const float* b1r          = (const float*)d_in[10];
    const float* W2r          = (const float*)d_in[11];
    const float* b2r          = (const float*)d_in[12];
    float* out = (float*)d_out;

    prep_w_kernel<<<512, 256>>>(W1t, W1r);

    cudaFuncSetAttribute(parser_hmma_kernel,
                         cudaFuncAttributeMaxDynamicSharedMemorySize, SMEM_TOTAL);
    dim3 grid(B_TOT / BM, 2);
    parser_hmma_kernel<<<grid, THREADS, SMEM_TOTAL>>>(
        lstm_out, stack_index, stack_len, buffer_index, buffer_len,
        b1t, W2t, b2t, b1r, W2r, b2r, out);
}

// round 14
// speedup vs baseline: 2.8214x; 1.5275x over previous
#include <cuda_runtime.h>
#include <cuda_fp16.h>
#include <stdint.h>

// Problem constants
#define B_TOT   4096
#define T_      64
#define D_      250
#define K_      1000
#define H_      125
#define NT      4
#define NL      50

// Tiling
#define BM      32
#define BN      128
#define KCH     128
#define NCHUNK  8
#define THREADS 512

// smem layout (bytes)
#define OFF_A    0                    // mainloop: [buf2][8192] fp16 A -> 16384
#define OFF_B    16384                // mainloop: [buf2][32768] -> 65536
#define OFF_SOFF 81920                // 32*4 ints
#define SMEM_TOTAL (81920 + 512)
// epilogue reuse:
#define OFF_RS   OFF_A                // reduction buffers (<=16KB)
#define OFF_HF   OFF_B                // Hs fp16 [2 panels][32x128B] = 8192
#define OFF_W2I  (OFF_B + 8192)       // W2 fp16 image [128][128B] = 16384

#define SW128(x) ((x) ^ ((((uint32_t)(x)) >> 3) & 0x70))

// Pre-swizzled W1 fp16 images: [half][chunk8][kpanel2][npanel2][8192]
__device__ __align__(16) uint8_t g_wbf[(size_t)2 * 8 * 32768];
// Pre-swizzled W2 fp16 images: [half][128 rows x 128B] = 2 x 16KB
__device__ __align__(16) uint8_t g_w2f[(size_t)2 * 16384];

__device__ __forceinline__ uint32_t smem_u32(const void* p) {
    uint32_t a;
    asm("{ .reg .u64 t; cvta.to.shared.u64 t, %1; cvt.u32.u64 %0, t; }"
        : "=r"(a) : "l"(p));
    return a;
}
__device__ __forceinline__ void ldsm4(uint32_t r[4], uint32_t a) {
    asm volatile("ldmatrix.sync.aligned.m8n8.x4.shared.b16 {%0,%1,%2,%3}, [%4];"
        : "=r"(r[0]), "=r"(r[1]), "=r"(r[2]), "=r"(r[3]) : "r"(a));
}
__device__ __forceinline__ void ldsm4t(uint32_t r[4], uint32_t a) {
    asm volatile("ldmatrix.sync.aligned.m8n8.x4.trans.shared.b16 {%0,%1,%2,%3}, [%4];"
        : "=r"(r[0]), "=r"(r[1]), "=r"(r[2]), "=r"(r[3]) : "r"(a));
}
__device__ __forceinline__ void mma16816(float c[4], const uint32_t a[4],
                                         uint32_t b0, uint32_t b1) {
    asm volatile(
        "mma.sync.aligned.m16n8k16.row.col.f32.f16.f16.f32 "
        "{%0,%1,%2,%3}, {%4,%5,%6,%7}, {%8,%9}, {%0,%1,%2,%3};"
        : "+f"(c[0]), "+f"(c[1]), "+f"(c[2]), "+f"(c[3])
        : "r"(a[0]), "r"(a[1]), "r"(a[2]), "r"(a[3]), "r"(b0), "r"(b1));
}
__device__ __forceinline__ void cp_async16(uint32_t s, const void* g) {
    asm volatile("cp.async.cg.shared.global [%0], [%1], 16;" :: "r"(s), "l"(g) : "memory");
}
__device__ __forceinline__ void cp_commit() {
    asm volatile("cp.async.commit_group;" ::: "memory");
}
template <int N> __device__ __forceinline__ void cp_wait() {
    asm volatile("cp.async.wait_group %0;" :: "n"(N) : "memory");
}
__device__ __forceinline__ uint32_t pack_h2(__half a, __half b) {
    __half2 h2 = __halves2half2(a, b);
    return *(uint32_t*)&h2;
}

// ------- prep: W1 chunk images + W2 image (fp16, swizzled, zero-padded) -------
__global__ void prep_w_kernel(const float* __restrict__ W1t,
                              const float* __restrict__ W1r,
                              const float* __restrict__ W2t,
                              const float* __restrict__ W2r)
{
    if (blockIdx.x < 512) {
        int idx  = blockIdx.x * 256 + threadIdx.x;   // 0..131071
        int np   = idx & 63;
        int k    = (idx >> 6) & 1023;
        int half = idx >> 16;
        const float* W1 = half ? W1r : W1t;

        int n0 = np * 2;
        float w0 = 0.f, w1 = 0.f;
        if (k < K_) {
            if (n0 < H_)     w0 = W1[k * H_ + n0];
            if (n0 + 1 < H_) w1 = W1[k * H_ + n0 + 1];
        }
        int chunk  = k >> 7;
        int kpanel = (k >> 6) & 1;
        int kloc   = k & 63;
        int npanel = n0 >> 6, nloc = n0 & 63;
        uint32_t sw = SW128((uint32_t)(kloc * 128 + nloc * 2));
        size_t o = ((size_t)half * 8 + chunk) * 32768
                 + (size_t)kpanel * 16384 + (size_t)npanel * 8192 + sw;
        *(uint32_t*)(g_wbf + o) = pack_h2(__float2half_rn(w0), __float2half_rn(w1));
    } else {
        int idx  = (blockIdx.x - 512) * 256 + threadIdx.x;   // 0..8191
        int np   = idx & 31;
        int k    = (idx >> 5) & 127;
        int half = idx >> 12;
        const float* W2 = half ? W2r : W2t;
        const int NO = half ? NL : NT;

        int n0 = np * 2;
        float w0 = 0.f, w1 = 0.f;
        if (k < H_) {
            if (n0 < NO)     w0 = W2[k * NO + n0];
            if (n0 + 1 < NO) w1 = W2[k * NO + n0 + 1];
        }
        uint32_t sw = SW128((uint32_t)(k * 128 + n0 * 2));
        *(uint32_t*)(g_w2f + (size_t)half * 16384 + sw) =
            pack_h2(__float2half_rn(w0), __float2half_rn(w1));
    }
}

// -- main: 512 thr, warps = 2(M) x 4(N) x 2(Ksplit), fp16, HMMA layer 2 --
__global__ __launch_bounds__(THREADS, 2)
void parser_hmma_kernel(const float* __restrict__ lstm_out,
                        const int*   __restrict__ stack_index,
                        const int*   __restrict__ stack_len,
                        const int*   __restrict__ buffer_index,
                        const int*   __restrict__ buffer_len,
                        const float* __restrict__ b1t,
                        const float* __restrict__ b2t,
                        const float* __restrict__ b1r,
                        const float* __restrict__ b2r,
                        float* __restrict__ out)
{
    extern __shared__ char smem[];
    const uint32_t sb = smem_u32(smem);
    const int tid  = threadIdx.x;
    const int wid  = tid >> 5;
    const int lane = tid & 31;
    const int ksp  = wid & 1;
    const int wm   = (wid >> 1) & 1;
    const int wn   = wid >> 2;
    const int b0   = blockIdx.x * BM;
    const int half = blockIdx.y;

    int* soff = (int*)(smem + OFF_SOFF);
    if (tid < BM * 4) {
        int row = tid >> 2, s = tid & 3;
        int b = b0 + row;
        int t, valid;
        if (s < 3) { valid = (s < stack_len[b]);  t = stack_index[b * 3 + s]; }
        else       { valid = (0 < buffer_len[b]); t = buffer_index[b]; }
        soff[tid] = valid ? (b * T_ + t) * D_ : -1;
    }
    __syncthreads();

    // A-gather geometry
    const int kp     = tid & 63;
    const int mbase  = tid >> 6;
    const uint32_t swstbase = (uint32_t)(kp >> 5) * 4096
                            + SW128((uint32_t)(mbase * 128 + (kp & 31) * 4));

    // ldmatrix geometry
    const int g = lane >> 3, r8 = lane & 7;
    const int arow = wm * 16 + (g & 1) * 8 + r8;
    const int acol = (g >> 1) * 8;
    const int brow = (g & 1) * 8 + r8;
    const int bc0  = ((wn * 32) & 63) + (g >> 1) * 8;
    const uint32_t bnp = (uint32_t)(wn >> 1) * 8192;

    uint32_t aoff[4], boff0[4], boff1[4];
    #pragma unroll
    for (int kk = 0; kk < 4; ++kk) {
        int kb = kk * 16;
        aoff[kk]  = SW128((uint32_t)(arow * 128 + (kb + acol) * 2));
        boff0[kk] = SW128((uint32_t)((kb + brow) * 128 + bc0 * 2));
        boff1[kk] = SW128((uint32_t)((kb + brow) * 128 + (bc0 + 16) * 2));
    }

    float acc[4][4];
    #pragma unroll
    for (int j = 0; j < 4; ++j)
        #pragma unroll
        for (int e = 0; e < 4; ++e) acc[j][e] = 0.f;

    auto loadA = [&](int c, float2 (&rv)[4]) {
        int k = c * KCH + 2 * kp;
        #pragma unroll
        for (int it = 0; it < 4; ++it) rv[it] = make_float2(0.f, 0.f);
        if (k < K_) {
            int slot = k / D_;
            int d    = k - slot * D_;
            #pragma unroll
            for (int it = 0; it < 4; ++it) {
                int m   = it * 8 + mbase;
                int off = soff[m * 4 + slot];
                if (off >= 0) rv[it] = *(const float2*)(lstm_out + off + d);
            }
        }
    };
    auto storeA = [&](int c, const float2 (&rv)[4]) {
        char* ah = smem + OFF_A + (c & 1) * 8192;
        #pragma unroll
        for (int it = 0; it < 4; ++it) {
            float2 v = rv[it];
            *(uint32_t*)(ah + swstbase + it * 1024) =
                pack_h2(__float2half_rn(v.x), __float2half_rn(v.y));
        }
    };
    auto fillB = [&](int c) {
        uint32_t dh = sb + OFF_B + (c & 1) * 32768;
        const uint8_t* sh = g_wbf + ((size_t)half * 8 + c) * 32768;
        #pragma unroll
        for (int it = 0; it < 4; ++it) {
            int o = (it * THREADS + tid) * 16;
            cp_async16(dh + o, sh + o);
        }
    };

    // prologue
    float2 rv[4];
    fillB(0); cp_commit();
    loadA(0, rv);

    #pragma unroll 2
    for (int c = 0; c < NCHUNK; ++c) {
        storeA(c, rv);
        if (c + 1 < NCHUNK) loadA(c + 1, rv);

        __syncthreads();                  // S1: B buffer (c+1)&1 free
        if (c + 1 < NCHUNK) {
            fillB(c + 1); cp_commit();
            cp_wait<1>();
        } else {
            cp_wait<0>();
        }
        __syncthreads();                  // S2: A stores + B fills visible

        int buf = c & 1;
        uint32_t ah = sb + OFF_A + buf * 8192 + ksp * 4096;
        uint32_t bh = sb + OFF_B + buf * 32768 + ksp * 16384 + bnp;

        #pragma unroll
        for (int kk = 0; kk < 4; ++kk) {
            uint32_t Ah[4], Bh[2][4];
            ldsm4(Ah, ah + aoff[kk]);
            ldsm4t(Bh[0], bh + boff0[kk]);
            ldsm4t(Bh[1], bh + boff1[kk]);
            #pragma unroll
            for (int j = 0; j < 4; ++j)
                mma16816(acc[j], Ah, Bh[j >> 1][(j & 1) * 2], Bh[j >> 1][(j & 1) * 2 + 1]);
        }
    }
    __syncthreads();   // mainloop done; A+B regions free

    // ---- kick off W2 image fill (16 KB -> OFF_W2I) ----
    {
        uint32_t d = sb + OFF_W2I;
        const uint8_t* s = g_w2f + (size_t)half * 16384;
        int o = tid * 16;
        cp_async16(d + o, s + o);
        cp_async16(d + 8192 + o, s + 8192 + o);
        cp_commit();
    }

    // ---- layer-1 K-split reduction (Rs at OFF_A) ----
    float* Rs = (float*)(smem + OFF_RS);
    const int pairIdx = wid >> 1;
    if (ksp == 1) {
        float* dst = Rs + (pairIdx * 32 + lane) * 16;
        #pragma unroll
        for (int j = 0; j < 4; ++j)
            *(float4*)(dst + j * 4) = make_float4(acc[j][0], acc[j][1], acc[j][2], acc[j][3]);
    }
    __syncthreads();
    const float* b1 = half ? b1r : b1t;
    if (ksp == 0) {
        const float* src = Rs + (pairIdx * 32 + lane) * 16;
        #pragma unroll
        for (int j = 0; j < 4; ++j) {
            float4 v = *(const float4*)(src + j * 4);
            acc[j][0] += v.x; acc[j][1] += v.y; acc[j][2] += v.z; acc[j][3] += v.w;
        }
        // bias + tanh -> fp16 Hs panels at OFF_HF (cols >= 125 are exactly 0)
        #pragma unroll
        for (int j = 0; j < 4; ++j) {
            int row = wm * 16 + (lane >> 2);
            int col = wn * 32 + j * 8 + (lane & 3) * 2;
            float bv0 = (col < H_)     ? __ldg(b1 + col)     : 0.f;
            float bv1 = (col + 1 < H_) ? __ldg(b1 + col + 1) : 0.f;
            uint32_t base = (uint32_t)(col >> 6) * 4096;
            uint32_t sw0 = base + SW128((uint32_t)(row * 128 + (col & 63) * 2));
            uint32_t sw8 = base + SW128((uint32_t)((row + 8) * 128 + (col & 63) * 2));
            *(uint32_t*)(smem + OFF_HF + sw0) =
                pack_h2(__float2half_rn(tanhf(acc[j][0] + bv0)),
                        __float2half_rn(tanhf(acc[j][1] + bv1)));
            *(uint32_t*)(smem + OFF_HF + sw8) =
                pack_h2(__float2half_rn(tanhf(acc[j][2] + bv0)),
                        __float2half_rn(tanhf(acc[j][3] + bv1)));
        }
    }
    cp_wait<0>();
    __syncthreads();   // Hs + W2 image ready; Rs reads done

    // ---- layer 2 on tensor pipe: [32 x 64] = Hs[32 x 128] @ W2[128 x 64] ----
    const int m2 = wid & 1;           // rows m2*16..
    const int n4 = (wid >> 1) & 3;    // cols n4*16..
    const int kh = wid >> 3;          // k-half 0/1
    float acc2[2][4];
    #pragma unroll
    for (int j = 0; j < 2; ++j)
        #pragma unroll
        for (int e = 0; e < 4; ++e) acc2[j][e] = 0.f;

    {
        const int arow2 = m2 * 16 + (g & 1) * 8 + r8;
        const int bc2   = n4 * 16 + (g >> 1) * 8;
        uint32_t ha = sb + OFF_HF + (uint32_t)kh * 4096;
        uint32_t wb = sb + OFF_W2I;
        #pragma unroll
        for (int kk = 0; kk < 4; ++kk) {
            int kloc  = kk * 16;
            int kglob = kh * 64 + kloc;
            uint32_t Ah2[4], Bh2[4];
            ldsm4(Ah2, ha + SW128((uint32_t)(arow2 * 128 + (kloc + acol) * 2)));
            ldsm4t(Bh2, wb + SW128((uint32_t)((kglob + brow) * 128 + bc2 * 2)));
            mma16816(acc2[0], Ah2, Bh2[0], Bh2[1]);
            mma16816(acc2[1], Ah2, Bh2[2], Bh2[3]);
        }
    }

    // ---- layer-2 K-half reduction ----
    float* Rs2 = (float*)(smem + OFF_RS);   // 8 pairs x 32 x 8 floats = 8KB
    const int pair2 = wid & 7;
    if (kh == 1) {
        float* dst = Rs2 + (pair2 * 32 + lane) * 8;
        #pragma unroll
        for (int j = 0; j < 2; ++j)
            *(float4*)(dst + j * 4) = make_float4(acc2[j][0], acc2[j][1], acc2[j][2], acc2[j][3]);
    }
    __syncthreads();

    const int NO = half ? NL : NT;
    const float* b2 = half ? b2r : b2t;
    float* obase = half ? (out + B_TOT * NT) : out;

    if (kh == 0) {
        const float* src = Rs2 + (pair2 * 32 + lane) * 8;
        #pragma unroll
        for (int j = 0; j < 2; ++j) {
            float4 v = *(const float4*)(src + j * 4);
            acc2[j][0] += v.x; acc2[j][1] += v.y; acc2[j][2] += v.z; acc2[j][3] += v.w;
        }
        #pragma unroll
        for (int j = 0; j < 2; ++j) {
            int row = m2 * 16 + (lane >> 2);
            int col = n4 * 16 + j * 8 + (lane & 3) * 2;
            if (col < NO) {
                float bv0 = __ldg(b2 + col);
                obase[(b0 + row) * NO + col]     = tanhf(acc2[j][0] + bv0);
                obase[(b0 + row + 8) * NO + col] = tanhf(acc2[j][2] + bv0);
                if (col + 1 < NO) {
                    float bv1 = __ldg(b2 + col + 1);
                    obase[(b0 + row) * NO + col + 1]     = tanhf(acc2[j][1] + bv1);
                    obase[(b0 + row + 8) * NO + col + 1] = tanhf(acc2[j][3] + bv1);
                }
            }
        }
    }
}

extern "C" void kernel_launch(void* const* d_in, const int* in_sizes, int n_in,
                              void* d_out, int out_size)
{
    const float* lstm_out     = (const float*)d_in[0];
    const int*   stack_index  = (const int*)  d_in[1];
    const int*   stack_len    = (const int*)  d_in[2];
    const int*   buffer_index = (const int*)  d_in[3];
    const int*   buffer_len   = (const int*)  d_in[4];
    const float* W1t          = (const float*)d_in[5];
    const float* b1t          = (const float*)d_in[6];
    const float* W2t          = (const float*)d_in[7];
    const float* b2t          = (const float*)d_in[8];
    const float* W1r          = (const float*)d_in[9];
    const float* b1r          = (const float*)d_in[10];
    const float* W2r          = (const float*)d_in[11];
    const float* b2r          = (const float*)d_in[12];
    float* out = (float*)d_out;

    prep_w_kernel<<<544, 256>>>(W1t, W1r, W2t, W2r);

    cudaFuncSetAttribute(parser_hmma_kernel,
                         cudaFuncAttributeMaxDynamicSharedMemorySize, SMEM_TOTAL);
    dim3 grid(B_TOT / BM, 2);
    parser_hmma_kernel<<<grid, THREADS, SMEM_TOTAL>>>(
        lstm_out, stack_index, stack_len, buffer_index, buffer_len,
        b1t, b2t, b1r, b2r, out);
}

// round 15
// speedup vs baseline: 2.8253x; 1.0014x over previous
#include <cuda_runtime.h>
#include <cuda_fp16.h>
#include <stdint.h>

// Problem constants
#define B_TOT   4096
#define T_      64
#define D_      250
#define K_      1000
#define H_      125
#define NT      4
#define NL      50

// Tiling
#define BM      32
#define BN      128
#define KCH     128
#define NCHUNK  8
#define THREADS 512

// smem layout (bytes)
#define OFF_A    0                    // [buf2][8192] fp16 A -> 16384
#define OFF_B    16384                // [buf3][32768] -> 98304
#define OFF_SOFF 114688               // 32*4 ints
#define SMEM_TOTAL (114688 + 512)
// epilogue reuse:
#define OFF_RS   OFF_A                // reduction buffers (<=16KB)
#define OFF_HF   OFF_B                // Hs fp16 [2 panels][32x128B] = 8192
#define OFF_W2I  (OFF_B + 8192)       // W2 fp16 image [128][128B] = 16384

#define SW128(x) ((x) ^ ((((uint32_t)(x)) >> 3) & 0x70))

// Pre-swizzled W1 fp16 images: [half][chunk8][kpanel2][npanel2][8192]
__device__ __align__(16) uint8_t g_wbf[(size_t)2 * 8 * 32768];
// Pre-swizzled W2 fp16 images: [half][128 rows x 128B] = 2 x 16KB
__device__ __align__(16) uint8_t g_w2f[(size_t)2 * 16384];

__device__ __forceinline__ uint32_t smem_u32(const void* p) {
    uint32_t a;
    asm("{ .reg .u64 t; cvta.to.shared.u64 t, %1; cvt.u32.u64 %0, t; }"
        : "=r"(a) : "l"(p));
    return a;
}
__device__ __forceinline__ void ldsm4(uint32_t r[4], uint32_t a) {
    asm volatile("ldmatrix.sync.aligned.m8n8.x4.shared.b16 {%0,%1,%2,%3}, [%4];"
        : "=r"(r[0]), "=r"(r[1]), "=r"(r[2]), "=r"(r[3]) : "r"(a));
}
__device__ __forceinline__ void ldsm4t(uint32_t r[4], uint32_t a) {
    asm volatile("ldmatrix.sync.aligned.m8n8.x4.trans.shared.b16 {%0,%1,%2,%3}, [%4];"
        : "=r"(r[0]), "=r"(r[1]), "=r"(r[2]), "=r"(r[3]) : "r"(a));
}
__device__ __forceinline__ void mma16816(float c[4], const uint32_t a[4],
                                         uint32_t b0, uint32_t b1) {
    asm volatile(
        "mma.sync.aligned.m16n8k16.row.col.f32.f16.f16.f32 "
        "{%0,%1,%2,%3}, {%4,%5,%6,%7}, {%8,%9}, {%0,%1,%2,%3};"
        : "+f"(c[0]), "+f"(c[1]), "+f"(c[2]), "+f"(c[3])
        : "r"(a[0]), "r"(a[1]), "r"(a[2]), "r"(a[3]), "r"(b0), "r"(b1));
}
__device__ __forceinline__ void cp_async16(uint32_t s, const void* g) {
    asm volatile("cp.async.cg.shared.global [%0], [%1], 16;" :: "r"(s), "l"(g) : "memory");
}
__device__ __forceinline__ void cp_commit() {
    asm volatile("cp.async.commit_group;" ::: "memory");
}
template <int N> __device__ __forceinline__ void cp_wait() {
    asm volatile("cp.async.wait_group %0;" :: "n"(N) : "memory");
}
__device__ __forceinline__ uint32_t pack_h2(__half a, __half b) {
    __half2 h2 = __halves2half2(a, b);
    return *(uint32_t*)&h2;
}

// ------- prep: W1 chunk images + W2 image (fp16, swizzled, zero-padded) -------
__global__ void prep_w_kernel(const float* __restrict__ W1t,
                              const float* __restrict__ W1r,
                              const float* __restrict__ W2t,
                              const float* __restrict__ W2r)
{
    if (blockIdx.x < 512) {
        int idx  = blockIdx.x * 256 + threadIdx.x;   // 0..131071
        int np   = idx & 63;
        int k    = (idx >> 6) & 1023;
        int half = idx >> 16;
        const float* W1 = half ? W1r : W1t;

        int n0 = np * 2;
        float w0 = 0.f, w1 = 0.f;
        if (k < K_) {
            if (n0 < H_)     w0 = W1[k * H_ + n0];
            if (n0 + 1 < H_) w1 = W1[k * H_ + n0 + 1];
        }
        int chunk  = k >> 7;
        int kpanel = (k >> 6) & 1;
        int kloc   = k & 63;
        int npanel = n0 >> 6, nloc = n0 & 63;
        uint32_t sw = SW128((uint32_t)(kloc * 128 + nloc * 2));
        size_t o = ((size_t)half * 8 + chunk) * 32768
                 + (size_t)kpanel * 16384 + (size_t)npanel * 8192 + sw;
        *(uint32_t*)(g_wbf + o) = pack_h2(__float2half_rn(w0), __float2half_rn(w1));
    } else {
        int idx  = (blockIdx.x - 512) * 256 + threadIdx.x;   // 0..8191
        int np   = idx & 31;
        int k    = (idx >> 5) & 127;
        int half = idx >> 12;
        const float* W2 = half ? W2r : W2t;
        const int NO = half ? NL : NT;

        int n0 = np * 2;
        float w0 = 0.f, w1 = 0.f;
        if (k < H_) {
            if (n0 < NO)     w0 = W2[k * NO + n0];
            if (n0 + 1 < NO) w1 = W2[k * NO + n0 + 1];
        }
        uint32_t sw = SW128((uint32_t)(k * 128 + n0 * 2));
        *(uint32_t*)(g_w2f + (size_t)half * 16384 + sw) =
            pack_h2(__float2half_rn(w0), __float2half_rn(w1));
    }
}

// -- main: 512 thr, 2(M)x4(N)x2(Ksplit), fp16, 3-stage B, 1 barrier/chunk --
__global__ __launch_bounds__(THREADS, 2)
void parser_hmma_kernel(const float* __restrict__ lstm_out,
                        const int*   __restrict__ stack_index,
                        const int*   __restrict__ stack_len,
                        const int*   __restrict__ buffer_index,
                        const int*   __restrict__ buffer_len,
                        const float* __restrict__ b1t,
                        const float* __restrict__ b2t,
                        const float* __restrict__ b1r,
                        const float* __restrict__ b2r,
                        float* __restrict__ out)
{
    extern __shared__ char smem[];
    const uint32_t sb = smem_u32(smem);
    const int tid  = threadIdx.x;
    const int wid  = tid >> 5;
    const int lane = tid & 31;
    const int ksp  = wid & 1;
    const int wm   = (wid >> 1) & 1;
    const int wn   = wid >> 2;
    const int b0   = blockIdx.x * BM;
    const int half = blockIdx.y;

    int* soff = (int*)(smem + OFF_SOFF);
    if (tid < BM * 4) {
        int row = tid >> 2, s = tid & 3;
        int b = b0 + row;
        int t, valid;
        if (s < 3) { valid = (s < stack_len[b]);  t = stack_index[b * 3 + s]; }
        else       { valid = (0 < buffer_len[b]); t = buffer_index[b]; }
        soff[tid] = valid ? (b * T_ + t) * D_ : -1;
    }
    __syncthreads();

    // A-gather geometry
    const int kp     = tid & 63;
    const int mbase  = tid >> 6;
    const uint32_t swstbase = (uint32_t)(kp >> 5) * 4096
                            + SW128((uint32_t)(mbase * 128 + (kp & 31) * 4));

    // ldmatrix geometry
    const int g = lane >> 3, r8 = lane & 7;
    const int arow = wm * 16 + (g & 1) * 8 + r8;
    const int acol = (g >> 1) * 8;
    const int brow = (g & 1) * 8 + r8;
    const int bc0  = ((wn * 32) & 63) + (g >> 1) * 8;
    const uint32_t bnp = (uint32_t)(wn >> 1) * 8192;

    uint32_t aoff[4], boff0[4], boff1[4];
    #pragma unroll
    for (int kk = 0; kk < 4; ++kk) {
        int kb = kk * 16;
        aoff[kk]  = SW128((uint32_t)(arow * 128 + (kb + acol) * 2));
        boff0[kk] = SW128((uint32_t)((kb + brow) * 128 + bc0 * 2));
        boff1[kk] = SW128((uint32_t)((kb + brow) * 128 + (bc0 + 16) * 2));
    }

    float acc[4][4];
    #pragma unroll
    for (int j = 0; j < 4; ++j)
        #pragma unroll
        for (int e = 0; e < 4; ++e) acc[j][e] = 0.f;

    auto loadA = [&](int c, float2 (&rv)[4]) {
        int k = c * KCH + 2 * kp;
        #pragma unroll
        for (int it = 0; it < 4; ++it) rv[it] = make_float2(0.f, 0.f);
        if (k < K_) {
            int slot = k / D_;
            int d    = k - slot * D_;
            #pragma unroll
            for (int it = 0; it < 4; ++it) {
                int m   = it * 8 + mbase;
                int off = soff[m * 4 + slot];
                if (off >= 0) rv[it] = *(const float2*)(lstm_out + off + d);
            }
        }
    };
    auto storeA = [&](int c, const float2 (&rv)[4]) {
        char* ah = smem + OFF_A + (c & 1) * 8192;
        #pragma unroll
        for (int it = 0; it < 4; ++it) {
            float2 v = rv[it];
            *(uint32_t*)(ah + swstbase + it * 1024) =
                pack_h2(__float2half_rn(v.x), __float2half_rn(v.y));
        }
    };
    auto fillB = [&](int c, int buf) {
        uint32_t dh = sb + OFF_B + buf * 32768;
        const uint8_t* sh = g_wbf + ((size_t)half * 8 + c) * 32768;
        #pragma unroll
        for (int it = 0; it < 4; ++it) {
            int o = (it * THREADS + tid) * 16;
            cp_async16(dh + o, sh + o);
        }
    };

    // prologue: B(0), B(1) in flight (2 groups), A(0) to regs
    float2 rv[4];
    fillB(0, 0); cp_commit();
    fillB(1, 1); cp_commit();
    loadA(0, rv);

    int bufc = 0;   // buffer holding chunk c
    int buff = 2;   // buffer for chunk c+2 fill
    for (int c = 0; c < NCHUNK; ++c) {
        storeA(c, rv);
        if (c + 1 < NCHUNK) loadA(c + 1, rv);

        cp_wait<1>();            // own copies of B(c) done
        __syncthreads();         // publish all fills + all warps done chunk c-1

        if (c + 2 < NCHUNK) fillB(c + 2, buff);
        cp_commit();             // one group per iteration (possibly empty)

        uint32_t ah = sb + OFF_A + (c & 1) * 8192 + ksp * 4096;
        uint32_t bh = sb + OFF_B + bufc * 32768 + ksp * 16384 + bnp;

        #pragma unroll
        for (int kk = 0; kk < 4; ++kk) {
            uint32_t Ah[4], Bh[2][4];
            ldsm4(Ah, ah + aoff[kk]);
            ldsm4t(Bh[0], bh + boff0[kk]);
            ldsm4t(Bh[1], bh + boff1[kk]);
            #pragma unroll
            for (int j = 0; j < 4; ++j)
                mma16816(acc[j], Ah, Bh[j >> 1][(j & 1) * 2], Bh[j >> 1][(j & 1) * 2 + 1]);
        }

        if (++bufc == 3) bufc = 0;
        if (++buff == 3) buff = 0;
    }
    __syncthreads();   // mainloop done; A+B regions free

    // ---- kick off W2 image fill (16 KB -> OFF_W2I) ----
    {
        uint32_t d = sb + OFF_W2I;
        const uint8_t* s = g_w2f + (size_t)half * 16384;
        int o = tid * 16;
        cp_async16(d + o, s + o);
        cp_async16(d + 8192 + o, s + 8192 + o);
        cp_commit();
    }

    // ---- layer-1 K-split reduction (Rs at OFF_A) ----
    float* Rs = (float*)(smem + OFF_RS);
    const int pairIdx = wid >> 1;
    if (ksp == 1) {
        float* dst = Rs + (pairIdx * 32 + lane) * 16;
        #pragma unroll
        for (int j = 0; j < 4; ++j)
            *(float4*)(dst + j * 4) = make_float4(acc[j][0], acc[j][1], acc[j][2], acc[j][3]);
    }
    __syncthreads();
    const float* b1 = half ? b1r : b1t;
    if (ksp == 0) {
        const float* src = Rs + (pairIdx * 32 + lane) * 16;
        #pragma unroll
        for (int j = 0; j < 4; ++j) {
            float4 v = *(const float4*)(src + j * 4);
            acc[j][0] += v.x; acc[j][1] += v.y; acc[j][2] += v.z; acc[j][3] += v.w;
        }
        // bias + tanh -> fp16 Hs panels at OFF_HF (cols >= 125 are exactly 0)
        #pragma unroll
        for (int j = 0; j < 4; ++j) {
            int row = wm * 16 + (lane >> 2);
            int col = wn * 32 + j * 8 + (lane & 3) * 2;
            float bv0 = (col < H_)     ? __ldg(b1 + col)     : 0.f;
            float bv1 = (col + 1 < H_) ? __ldg(b1 + col + 1) : 0.f;
            uint32_t base = (uint32_t)(col >> 6) * 4096;
            uint32_t sw0 = base + SW128((uint32_t)(row * 128 + (col & 63) * 2));
            uint32_t sw8 = base + SW128((uint32_t)((row + 8) * 128 + (col & 63) * 2));
            *(uint32_t*)(smem + OFF_HF + sw0) =
                pack_h2(__float2half_rn(tanhf(acc[j][0] + bv0)),
                        __float2half_rn(tanhf(acc[j][1] + bv1)));
            *(uint32_t*)(smem + OFF_HF + sw8) =
                pack_h2(__float2half_rn(tanhf(acc[j][2] + bv0)),
                        __float2half_rn(tanhf(acc[j][3] + bv1)));
        }
    }
    cp_wait<0>();
    __syncthreads();   // Hs + W2 image ready; Rs reads done

    // ---- layer 2 on tensor pipe: [32 x 64] = Hs[32 x 128] @ W2[128 x 64] ----
    const int m2 = wid & 1;
    const int n4 = (wid >> 1) & 3;
    const int kh = wid >> 3;
    float acc2[2][4];
    #pragma unroll
    for (int j = 0; j < 2; ++j)
        #pragma unroll
        for (int e = 0; e < 4; ++e) acc2[j][e] = 0.f;

    {
        const int arow2 = m2 * 16 + (g & 1) * 8 + r8;
        const int bc2   = n4 * 16 + (g >> 1) * 8;
        uint32_t ha = sb + OFF_HF + (uint32_t)kh * 4096;
        uint32_t wb = sb + OFF_W2I;
        #pragma unroll
        for (int kk = 0; kk < 4; ++kk) {
            int kloc  = kk * 16;
            int kglob = kh * 64 + kloc;
            uint32_t Ah2[4], Bh2[4];
            ldsm4(Ah2, ha + SW128((uint32_t)(arow2 * 128 + (kloc + acol) * 2)));
            ldsm4t(Bh2, wb + SW128((uint32_t)((kglob + brow) * 128 + bc2 * 2)));
            mma16816(acc2[0], Ah2, Bh2[0], Bh2[1]);
            mma16816(acc2[1], Ah2, Bh2[2], Bh2[3]);
        }
    }

    // ---- layer-2 K-half reduction ----
    float* Rs2 = (float*)(smem + OFF_RS);
    const int pair2 = wid & 7;
    if (kh == 1) {
        float* dst = Rs2 + (pair2 * 32 + lane) * 8;
        #pragma unroll
        for (int j = 0; j < 2; ++j)
            *(float4*)(dst + j * 4) = make_float4(acc2[j][0], acc2[j][1], acc2[j][2], acc2[j][3]);
    }
    __syncthreads();

    const int NO = half ? NL : NT;
    const float* b2 = half ? b2r : b2t;
    float* obase = half ? (out + B_TOT * NT) : out;

    if (kh == 0) {
        const float* src = Rs2 + (pair2 * 32 + lane) * 8;
        #pragma unroll
        for (int j = 0; j < 2; ++j) {
            float4 v = *(const float4*)(src + j * 4);
            acc2[j][0] += v.x; acc2[j][1] += v.y; acc2[j][2] += v.z; acc2[j][3] += v.w;
        }
        #pragma unroll
        for (int j = 0; j < 2; ++j) {
            int row = m2 * 16 + (lane >> 2);
            int col = n4 * 16 + j * 8 + (lane & 3) * 2;
            if (col < NO) {
                float bv0 = __ldg(b2 + col);
                obase[(b0 + row) * NO + col]     = tanhf(acc2[j][0] + bv0);
                obase[(b0 + row + 8) * NO + col] = tanhf(acc2[j][2] + bv0);
                if (col + 1 < NO) {
                    float bv1 = __ldg(b2 + col + 1);
                    obase[(b0 + row) * NO + col + 1]     = tanhf(acc2[j][1] + bv1);
                    obase[(b0 + row + 8) * NO + col + 1] = tanhf(acc2[j][3] + bv1);
                }
            }
        }
    }
}

extern "C" void kernel_launch(void* const* d_in, const int* in_sizes, int n_in,
                              void* d_out, int out_size)
{
    const float* lstm_out     = (const float*)d_in[0];
    const int*   stack_index  = (const int*)  d_in[1];
    const int*   stack_len    = (const int*)  d_in[2];
    const int*   buffer_index = (const int*)  d_in[3];
    const int*   buffer_len   = (const int*)  d_in[4];
    const float* W1t          = (const float*)d_in[5];
    const float* b1t          = (const float*)d_in[6];
    const float* W2t          = (const float*)d_in[7];
    const float* b2t          = (const float*)d_in[8];
    const float* W1r          = (const float*)d_in[9];
    const float* b1r          = (const float*)d_in[10];
    const float* W2r          = (const float*)d_in[11];
    const float* b2r          = (const float*)d_in[12];
    float* out = (float*)d_out;

    prep_w_kernel<<<544, 256>>>(W1t, W1r, W2t, W2r);

    cudaFuncSetAttribute(parser_hmma_kernel,
                         cudaFuncAttributeMaxDynamicSharedMemorySize, SMEM_TOTAL);
    dim3 grid(B_TOT / BM, 2);
    parser_hmma_kernel<<<grid, THREADS, SMEM_TOTAL>>>(
        lstm_out, stack_index, stack_len, buffer_index, buffer_len,
        b1t, b2t, b1r, b2r, out);
}

// round 16
// speedup vs baseline: 3.1359x; 1.1099x over previous
#include <cuda_runtime.h>
#include <cuda_fp16.h>
#include <stdint.h>

// Problem constants
#define B_TOT   4096
#define T_      64
#define D_      250
#define K_      1000
#define H_      125
#define NT      4
#define NL      50

// Tiling
#define BM      32
#define BN      128
#define KCH     128
#define NCHUNK  8
#define THREADS 512

// smem layout (bytes)
#define OFF_A    0                    // [buf2][8192] fp16 A -> 16384
#define OFF_B    16384                // [buf3][32768] -> 98304
#define OFF_SOFF 114688               // 32*4 ints
#define SMEM_TOTAL (114688 + 512)
// epilogue reuse:
#define OFF_RS   OFF_A                // reduction buffers (<=16KB)
#define OFF_HF   OFF_B                // Hs fp16 [2 panels][32x128B] = 8192
#define OFF_W2I  (OFF_B + 8192)       // W2 fp16 image [128][128B] = 16384

#define SW128(x) ((x) ^ ((((uint32_t)(x)) >> 3) & 0x70))

// Pre-swizzled W1 fp16 images: [half][chunk8][kpanel2][npanel2][8192]
__device__ __align__(16) uint8_t g_wbf[(size_t)2 * 8 * 32768];
// Pre-swizzled W2 fp16 images: [half][128 rows x 128B] = 2 x 16KB
__device__ __align__(16) uint8_t g_w2f[(size_t)2 * 16384];

__device__ __forceinline__ uint32_t smem_u32(const void* p) {
    uint32_t a;
    asm("{ .reg .u64 t; cvta.to.shared.u64 t, %1; cvt.u32.u64 %0, t; }"
        : "=r"(a) : "l"(p));
    return a;
}
__device__ __forceinline__ void ldsm4(uint32_t r[4], uint32_t a) {
    asm volatile("ldmatrix.sync.aligned.m8n8.x4.shared.b16 {%0,%1,%2,%3}, [%4];"
        : "=r"(r[0]), "=r"(r[1]), "=r"(r[2]), "=r"(r[3]) : "r"(a));
}
__device__ __forceinline__ void ldsm4t(uint32_t r[4], uint32_t a) {
    asm volatile("ldmatrix.sync.aligned.m8n8.x4.trans.shared.b16 {%0,%1,%2,%3}, [%4];"
        : "=r"(r[0]), "=r"(r[1]), "=r"(r[2]), "=r"(r[3]) : "r"(a));
}
__device__ __forceinline__ void mma16816(float c[4], const uint32_t a[4],
                                         uint32_t b0, uint32_t b1) {
    asm volatile(
        "mma.sync.aligned.m16n8k16.row.col.f32.f16.f16.f32 "
        "{%0,%1,%2,%3}, {%4,%5,%6,%7}, {%8,%9}, {%0,%1,%2,%3};"
        : "+f"(c[0]), "+f"(c[1]), "+f"(c[2]), "+f"(c[3])
        : "r"(a[0]), "r"(a[1]), "r"(a[2]), "r"(a[3]), "r"(b0), "r"(b1));
}
__device__ __forceinline__ void cp_async16(uint32_t s, const void* g) {
    asm volatile("cp.async.cg.shared.global [%0], [%1], 16;" :: "r"(s), "l"(g) : "memory");
}
__device__ __forceinline__ void cp_commit() {
    asm volatile("cp.async.commit_group;" ::: "memory");
}
template <int N> __device__ __forceinline__ void cp_wait() {
    asm volatile("cp.async.wait_group %0;" :: "n"(N) : "memory");
}
__device__ __forceinline__ uint32_t pack_h2(__half a, __half b) {
    __half2 h2 = __halves2half2(a, b);
    return *(uint32_t*)&h2;
}
__device__ __forceinline__ float tanh_fast(float x) {
    float y;
    asm("tanh.approx.f32 %0, %1;" : "=f"(y) : "f"(x));
    return y;
}

// ------- prep: W1 chunk images + W2 image (fp16, swizzled, zero-padded) -------
__global__ void prep_w_kernel(const float* __restrict__ W1t,
                              const float* __restrict__ W1r,
                              const float* __restrict__ W2t,
                              const float* __restrict__ W2r)
{
    if (blockIdx.x < 512) {
        int idx  = blockIdx.x * 256 + threadIdx.x;   // 0..131071
        int np   = idx & 63;
        int k    = (idx >> 6) & 1023;
        int half = idx >> 16;
        const float* W1 = half ? W1r : W1t;

        int n0 = np * 2;
        float w0 = 0.f, w1 = 0.f;
        if (k < K_) {
            if (n0 < H_)     w0 = W1[k * H_ + n0];
            if (n0 + 1 < H_) w1 = W1[k * H_ + n0 + 1];
        }
        int chunk  = k >> 7;
        int kpanel = (k >> 6) & 1;
        int kloc   = k & 63;
        int npanel = n0 >> 6, nloc = n0 & 63;
        uint32_t sw = SW128((uint32_t)(kloc * 128 + nloc * 2));
        size_t o = ((size_t)half * 8 + chunk) * 32768
                 + (size_t)kpanel * 16384 + (size_t)npanel * 8192 + sw;
        *(uint32_t*)(g_wbf + o) = pack_h2(__float2half_rn(w0), __float2half_rn(w1));
    } else {
        int idx  = (blockIdx.x - 512) * 256 + threadIdx.x;   // 0..8191
        int np   = idx & 31;
        int k    = (idx >> 5) & 127;
        int half = idx >> 12;
        const float* W2 = half ? W2r : W2t;
        const int NO = half ? NL : NT;

        int n0 = np * 2;
        float w0 = 0.f, w1 = 0.f;
        if (k < H_) {
            if (n0 < NO)     w0 = W2[k * NO + n0];
            if (n0 + 1 < NO) w1 = W2[k * NO + n0 + 1];
        }
        uint32_t sw = SW128((uint32_t)(k * 128 + n0 * 2));
        *(uint32_t*)(g_w2f + (size_t)half * 16384 + sw) =
            pack_h2(__float2half_rn(w0), __float2half_rn(w1));
    }
}

// -- main: 512 thr, 2(M)x4(N)x2(Ksplit), fp16, 3-stage B, fully unrolled --
__global__ __launch_bounds__(THREADS, 2)
void parser_hmma_kernel(const float* __restrict__ lstm_out,
                        const int*   __restrict__ stack_index,
                        const int*   __restrict__ stack_len,
                        const int*   __restrict__ buffer_index,
                        const int*   __restrict__ buffer_len,
                        const float* __restrict__ b1t,
                        const float* __restrict__ b2t,
                        const float* __restrict__ b1r,
                        const float* __restrict__ b2r,
                        float* __restrict__ out)
{
    extern __shared__ char smem[];
    const uint32_t sb = smem_u32(smem);
    const int tid  = threadIdx.x;
    const int wid  = tid >> 5;
    const int lane = tid & 31;
    const int ksp  = wid & 1;
    const int wm   = (wid >> 1) & 1;
    const int wn   = wid >> 2;
    const int b0   = blockIdx.x * BM;
    const int half = blockIdx.y;

    int* soff = (int*)(smem + OFF_SOFF);
    if (tid < BM * 4) {
        int row = tid >> 2, s = tid & 3;
        int b = b0 + row;
        int t, valid;
        if (s < 3) { valid = (s < stack_len[b]);  t = stack_index[b * 3 + s]; }
        else       { valid = (0 < buffer_len[b]); t = buffer_index[b]; }
        soff[tid] = valid ? (b * T_ + t) * D_ : -1;
    }
    __syncthreads();

    // A-gather geometry: 2 adjacent k-pairs x 2 m-rows per thread
    const int kpA   = (tid & 31) * 2;        // even k-pair; kpB = kpA+1
    const int mbase = tid >> 5;              // m in {mbase, mbase+16}
    // store addr (8B-aligned; two adjacent uint32 share a swizzle block)
    const uint32_t swst0 = (uint32_t)(kpA >> 5) * 4096
                         + SW128((uint32_t)(mbase * 128 + (kpA & 31) * 4));
    const uint32_t swst1 = (uint32_t)(kpA >> 5) * 4096
                         + SW128((uint32_t)((mbase + 16) * 128 + (kpA & 31) * 4));

    // ldmatrix geometry
    const int g = lane >> 3, r8 = lane & 7;
    const int arow = wm * 16 + (g & 1) * 8 + r8;
    const int acol = (g >> 1) * 8;
    const int brow = (g & 1) * 8 + r8;
    const int bc0  = ((wn * 32) & 63) + (g >> 1) * 8;
    const uint32_t bnp = (uint32_t)(wn >> 1) * 8192;

    uint32_t aoff[4], boff0[4], boff1[4];
    #pragma unroll
    for (int kk = 0; kk < 4; ++kk) {
        int kb = kk * 16;
        aoff[kk]  = SW128((uint32_t)(arow * 128 + (kb + acol) * 2));
        boff0[kk] = SW128((uint32_t)((kb + brow) * 128 + bc0 * 2));
        boff1[kk] = SW128((uint32_t)((kb + brow) * 128 + (bc0 + 16) * 2));
    }

    float acc[4][4];
    #pragma unroll
    for (int j = 0; j < 4; ++j)
        #pragma unroll
        for (int e = 0; e < 4; ++e) acc[j][e] = 0.f;

    auto loadA = [&](int c, float2 (&rv)[4]) {
        #pragma unroll
        for (int it = 0; it < 4; ++it) rv[it] = make_float2(0.f, 0.f);
        #pragma unroll
        for (int kq = 0; kq < 2; ++kq) {            // kpA, kpA+1
            int k = c * KCH + 2 * (kpA + kq);
            if (k < K_) {
                int slot = k / D_;
                int d    = k - slot * D_;
                int offa = soff[mbase * 4 + slot];
                int offb = soff[(mbase + 16) * 4 + slot];
                if (offa >= 0) rv[kq]     = *(const float2*)(lstm_out + offa + d);
                if (offb >= 0) rv[2 + kq] = *(const float2*)(lstm_out + offb + d);
            }
        }
    };
    auto storeA = [&](int c, const float2 (&rv)[4]) {
        char* ah = smem + OFF_A + (c & 1) * 8192;
        uint2 v0, v1;
        v0.x = pack_h2(__float2half_rn(rv[0].x), __float2half_rn(rv[0].y));
        v0.y = pack_h2(__float2half_rn(rv[1].x), __float2half_rn(rv[1].y));
        v1.x = pack_h2(__float2half_rn(rv[2].x), __float2half_rn(rv[2].y));
        v1.y = pack_h2(__float2half_rn(rv[3].x), __float2half_rn(rv[3].y));
        *(uint2*)(ah + swst0) = v0;
        *(uint2*)(ah + swst1) = v1;
    };
    auto fillB = [&](int c, int buf) {
        uint32_t dh = sb + OFF_B + buf * 32768;
        const uint8_t* sh = g_wbf + ((size_t)half * 8 + c) * 32768;
        #pragma unroll
        for (int it = 0; it < 4; ++it) {
            int o = (it * THREADS + tid) * 16;
            cp_async16(dh + o, sh + o);
        }
        cp_commit();
    };
    auto compute = [&](int c, int bufc) {
        uint32_t ah = sb + OFF_A + (c & 1) * 8192 + ksp * 4096;
        uint32_t bh = sb + OFF_B + bufc * 32768 + ksp * 16384 + bnp;
        #pragma unroll
        for (int kk = 0; kk < 4; ++kk) {
            uint32_t Ah[4], Bh[2][4];
            ldsm4(Ah, ah + aoff[kk]);
            ldsm4t(Bh[0], bh + boff0[kk]);
            ldsm4t(Bh[1], bh + boff1[kk]);
            #pragma unroll
            for (int j = 0; j < 4; ++j)
                mma16816(acc[j], Ah, Bh[j >> 1][(j & 1) * 2], Bh[j >> 1][(j & 1) * 2 + 1]);
        }
    };

    // prologue: B(0), B(1) in flight, A(0) to regs
    float2 rv[4];
    fillB(0, 0);
    fillB(1, 1);
    loadA(0, rv);

    // fully unrolled mainloop: compile-time buffer indices
    #pragma unroll
    for (int c = 0; c < NCHUNK; ++c) {
        const int bufc = c % 3;
        storeA(c, rv);
        if (c + 1 < NCHUNK) loadA(c + 1, rv);

        cp_wait<1>();            // own copies of B(c) done
        __syncthreads();         // publish fills + all warps done chunk c-1

        if (c + 2 < NCHUNK) fillB(c + 2, (c + 2) % 3);

        compute(c, bufc);
    }
    __syncthreads();   // mainloop done; A+B regions free

    // ---- kick off W2 image fill (16 KB -> OFF_W2I) ----
    {
        uint32_t d = sb + OFF_W2I;
        const uint8_t* s = g_w2f + (size_t)half * 16384;
        int o = tid * 16;
        cp_async16(d + o, s + o);
        cp_async16(d + 8192 + o, s + 8192 + o);
        cp_commit();
    }

    // ---- layer-1 K-split reduction (Rs at OFF_A) ----
    float* Rs = (float*)(smem + OFF_RS);
    const int pairIdx = wid >> 1;
    if (ksp == 1) {
        float* dst = Rs + (pairIdx * 32 + lane) * 16;
        #pragma unroll
        for (int j = 0; j < 4; ++j)
            *(float4*)(dst + j * 4) = make_float4(acc[j][0], acc[j][1], acc[j][2], acc[j][3]);
    }
    __syncthreads();
    const float* b1 = half ? b1r : b1t;
    if (ksp == 0) {
        const float* src = Rs + (pairIdx * 32 + lane) * 16;
        #pragma unroll
        for (int j = 0; j < 4; ++j) {
            float4 v = *(const float4*)(src + j * 4);
            acc[j][0] += v.x; acc[j][1] += v.y; acc[j][2] += v.z; acc[j][3] += v.w;
        }
        // bias + fast tanh -> fp16 Hs panels (cols >= 125 exactly 0)
        #pragma unroll
        for (int j = 0; j < 4; ++j) {
            int row = wm * 16 + (lane >> 2);
            int col = wn * 32 + j * 8 + (lane & 3) * 2;
            float bv0 = (col < H_)     ? __ldg(b1 + col)     : 0.f;
            float bv1 = (col + 1 < H_) ? __ldg(b1 + col + 1) : 0.f;
            uint32_t base = (uint32_t)(col >> 6) * 4096;
            uint32_t sw0 = base + SW128((uint32_t)(row * 128 + (col & 63) * 2));
            uint32_t sw8 = base + SW128((uint32_t)((row + 8) * 128 + (col & 63) * 2));
            *(uint32_t*)(smem + OFF_HF + sw0) =
                pack_h2(__float2half_rn(tanh_fast(acc[j][0] + bv0)),
                        __float2half_rn(tanh_fast(acc[j][1] + bv1)));
            *(uint32_t*)(smem + OFF_HF + sw8) =
                pack_h2(__float2half_rn(tanh_fast(acc[j][2] + bv0)),
                        __float2half_rn(tanh_fast(acc[j][3] + bv1)));
        }
    }
    cp_wait<0>();
    __syncthreads();   // Hs + W2 image ready; Rs reads done

    // ---- layer 2 on tensor pipe: [32 x 64] = Hs[32 x 128] @ W2[128 x 64] ----
    const int m2 = wid & 1;
    const int n4 = (wid >> 1) & 3;
    const int kh = wid >> 3;
    float acc2[2][4];
    #pragma unroll
    for (int j = 0; j < 2; ++j)
        #pragma unroll
        for (int e = 0; e < 4; ++e) acc2[j][e] = 0.f;

    {
        const int arow2 = m2 * 16 + (g & 1) * 8 + r8;
        const int bc2   = n4 * 16 + (g >> 1) * 8;
        uint32_t ha = sb + OFF_HF + (uint32_t)kh * 4096;
        uint32_t wb = sb + OFF_W2I;
        #pragma unroll
        for (int kk = 0; kk < 4; ++kk) {
            int kloc  = kk * 16;
            int kglob = kh * 64 + kloc;
            uint32_t Ah2[4], Bh2[4];
            ldsm4(Ah2, ha + SW128((uint32_t)(arow2 * 128 + (kloc + acol) * 2)));
            ldsm4t(Bh2, wb + SW128((uint32_t)((kglob + brow) * 128 + bc2 * 2)));
            mma16816(acc2[0], Ah2, Bh2[0], Bh2[1]);
            mma16816(acc2[1], Ah2, Bh2[2], Bh2[3]);
        }
    }

    // ---- layer-2 K-half reduction ----
    float* Rs2 = (float*)(smem + OFF_RS);
    const int pair2 = wid & 7;
    if (kh == 1) {
        float* dst = Rs2 + (pair2 * 32 + lane) * 8;
        #pragma unroll
        for (int j = 0; j < 2; ++j)
            *(float4*)(dst + j * 4) = make_float4(acc2[j][0], acc2[j][1], acc2[j][2], acc2[j][3]);
    }
    __syncthreads();

    const int NO = half ? NL : NT;
    const float* b2 = half ? b2r : b2t;
    float* obase = half ? (out + B_TOT * NT) : out;

    if (kh == 0) {
        const float* src = Rs2 + (pair2 * 32 + lane) * 8;
        #pragma unroll
        for (int j = 0; j < 2; ++j) {
            float4 v = *(const float4*)(src + j * 4);
            acc2[j][0] += v.x; acc2[j][1] += v.y; acc2[j][2] += v.z; acc2[j][3] += v.w;
        }
        #pragma unroll
        for (int j = 0; j < 2; ++j) {
            int row = m2 * 16 + (lane >> 2);
            int col = n4 * 16 + j * 8 + (lane & 3) * 2;
            if (col < NO) {
                float bv0 = __ldg(b2 + col);
                obase[(b0 + row) * NO + col]     = tanhf(acc2[j][0] + bv0);
                obase[(b0 + row + 8) * NO + col] = tanhf(acc2[j][2] + bv0);
                if (col + 1 < NO) {
                    float bv1 = __ldg(b2 + col + 1);
                    obase[(b0 + row) * NO + col + 1]     = tanhf(acc2[j][1] + bv1);
                    obase[(b0 + row + 8) * NO + col + 1] = tanhf(acc2[j][3] + bv1);
                }
            }
        }
    }
}

extern "C" void kernel_launch(void* const* d_in, const int* in_sizes, int n_in,
                              void* d_out, int out_size)
{
    const float* lstm_out     = (const float*)d_in[0];
    const int*   stack_index  = (const int*)  d_in[1];
    const int*   stack_len    = (const int*)  d_in[2];
    const int*   buffer_index = (const int*)  d_in[3];
    const int*   buffer_len   = (const int*)  d_in[4];
    const float* W1t          = (const float*)d_in[5];
    const float* b1t          = (const float*)d_in[6];
    const float* W2t          = (const float*)d_in[7];
    const float* b2t          = (const float*)d_in[8];
    const float* W1r          = (const float*)d_in[9];
    const float* b1r          = (const float*)d_in[10];
    const float* W2r          = (const float*)d_in[11];
    const float* b2r          = (const float*)d_in[12];
    float* out = (float*)d_out;

    prep_w_kernel<<<544, 256>>>(W1t, W1r, W2t, W2r);

    cudaFuncSetAttribute(parser_hmma_kernel,
                         cudaFuncAttributeMaxDynamicSharedMemorySize, SMEM_TOTAL);
    dim3 grid(B_TOT / BM, 2);
    parser_hmma_kernel<<<grid, THREADS, SMEM_TOTAL>>>(
        lstm_out, stack_index, stack_len, buffer_index, buffer_len,
        b1t, b2t, b1r, b2r, out);
}